// round 8
// baseline (speedup 1.0000x reference)
#include <cuda_runtime.h>
#include <math.h>

#define H 160           // B*G = 4*40 heads
#define C 13
#define T 1024
#define F 513           // rfft bins
#define NSIG (H * C)    // 2080 signals

typedef unsigned long long ull;

// ---------------- f32x2 packed math helpers (sm_103a FFMA2) ----------------
__device__ __forceinline__ ull pk2(float a, float b) {
    ull r;
    asm("mov.b64 %0, {%1, %2};" : "=l"(r) : "r"(__float_as_uint(a)), "r"(__float_as_uint(b)));
    return r;
}
__device__ __forceinline__ void upk2(ull v, float& a, float& b) {
    unsigned lo, hi;
    asm("mov.b64 {%0, %1}, %2;" : "=r"(lo), "=r"(hi) : "l"(v));
    a = __uint_as_float(lo);
    b = __uint_as_float(hi);
}
__device__ __forceinline__ ull fma2(ull a, ull b, ull c) {
    ull d;
    asm("fma.rn.f32x2 %0, %1, %2, %3;" : "=l"(d) : "l"(a), "l"(b), "l"(c));
    return d;
}

// ---------------- scratch (device globals: allowed; no runtime alloc) ------
__device__ float2 d_W[512];        // twiddles exp(-2*pi*i*k/1024)
__device__ float2 d_X[H * C * F];  // spectrum, layout [head][c][f]
__device__ float2 d_Q[H * C * F];
__device__ float2 d_K[H * C * F];
__device__ float2 d_V[H * C * F];
__device__ float2 d_O[H * C * F];

// score scratch: [head][rowgroup(17*8)][col(pitch 520)] float4 (4 rows/group)
#define NRG 136        // 17 blocks * 8 warps
#define SPITCH 520
__device__ float4 d_S[H * NRG * SPITCH];   // ~181 MB

// ---------------- twiddle init (double trig for precision) -----------------
__global__ void init_twiddles() {
    int k = threadIdx.x;  // 0..511
    double ang = -2.0 * 3.14159265358979323846 * (double)k / 1024.0;
    d_W[k] = make_float2((float)cos(ang), (float)sin(ang));
}

// ---------------- shared radix-2 DIT FFT core (1024 pts, 512 threads) ------
__device__ __forceinline__ void fft_stages(float2* a, bool inverse) {
    int tid = threadIdx.x;
#pragma unroll
    for (int s = 1; s <= 10; ++s) {
        __syncthreads();
        int half = 1 << (s - 1);
        int k = tid & (half - 1);
        int i0 = ((tid >> (s - 1)) << s) + k;
        float2 w = d_W[k << (10 - s)];
        if (inverse) w.y = -w.y;
        float2 u = a[i0];
        float2 v = a[i0 + half];
        float tr = w.x * v.x - w.y * v.y;
        float ti = w.x * v.y + w.y * v.x;
        a[i0]        = make_float2(u.x + tr, u.y + ti);
        a[i0 + half] = make_float2(u.x - tr, u.y - ti);
    }
    __syncthreads();
}

// ---------------- forward rfft: x[sig][0..1023] -> d_X[sig][0..512] --------
__global__ void fft_forward(const float* __restrict__ x) {
    __shared__ float2 a[1024];
    int sig = blockIdx.x;   // head*13 + c
    int tid = threadIdx.x;  // 0..511
    const float* xp = x + sig * 1024;
    a[__brev(tid) >> 22]       = make_float2(xp[tid], 0.f);
    a[__brev(tid + 512) >> 22] = make_float2(xp[tid + 512], 0.f);
    fft_stages(a, false);
    float2* Xp = d_X + sig * F;
    Xp[tid] = a[tid];
    if (tid == 0) Xp[512] = a[512];
}

// ---------------- QKV: [head][c][f] = sum_cin X[head][cin][f] * W[cin][c] --
__global__ void qkv_kernel(const float* __restrict__ wq,
                           const float* __restrict__ wk,
                           const float* __restrict__ wv) {
    __shared__ float ws[3][169];
    int tid = threadIdx.x;
    if (tid < 169) {
        ws[0][tid] = wq[tid];
        ws[1][tid] = wk[tid];
        ws[2][tid] = wv[tid];
    }
    __syncthreads();
    int head = blockIdx.y;
    int f = blockIdx.x * blockDim.x + tid;
    if (f >= F) return;
    float xr[13], xi[13];
#pragma unroll
    for (int c = 0; c < 13; ++c) {
        float2 v = d_X[(head * 13 + c) * F + f];
        xr[c] = v.x;
        xi[c] = v.y;
    }
#pragma unroll 1
    for (int co = 0; co < 13; ++co) {
        float qr = 0.f, qi = 0.f, kr = 0.f, ki = 0.f, vr = 0.f, vi = 0.f;
#pragma unroll
        for (int ci = 0; ci < 13; ++ci) {
            float a = ws[0][ci * 13 + co];
            qr = fmaf(xr[ci], a, qr); qi = fmaf(xi[ci], a, qi);
            float b = ws[1][ci * 13 + co];
            kr = fmaf(xr[ci], b, kr); ki = fmaf(xi[ci], b, ki);
            float g = ws[2][ci * 13 + co];
            vr = fmaf(xr[ci], g, vr); vi = fmaf(xi[ci], g, vi);
        }
        int o = (head * 13 + co) * F + f;
        d_Q[o] = make_float2(qr, qi);
        d_K[o] = make_float2(kr, ki);
        d_V[o] = make_float2(vr, vi);
    }
}

// ---------------- attention ------------------------------------------------
// 256 threads = 8 warps, 4 query rows per warp (f32x2-packed math).
// Whole-head K (then V) resident in smem (13 x 576 padded). Scores live in
// global scratch d_S; softmax fused into pass 2 (m in regs, l accumulated
// on the fly during the first c-half; exp recomputed in the second half).
// 3 __syncthreads total.
#define TRR 32   // rows per CTA
#define KPITCH 576

#define SM_KV_BYTES  (13 * KPITCH * 8)              // 59904
#define SM_Q_BYTES   (8 * 13 * 4 * 8)               //  3328
#define SM_TOTAL     (SM_KV_BYTES + SM_Q_BYTES)     // 63232

__global__ __launch_bounds__(256, 3) void attn_kernel() {
    extern __shared__ char smem_raw[];
    float2* kv  = (float2*)smem_raw;                        // [13][576]
    ull*    qpk = (ull*)(smem_raw + SM_KV_BYTES);           // [w][13][4]

    int head = blockIdx.y;
    int tid = threadIdx.x, lane = tid & 31, w = tid >> 5;
    int fbase = blockIdx.x * TRR + 4 * w;
    float4* srow = d_S + (size_t)((head * NRG) + blockIdx.x * 8 + w) * SPITCH;

    // ---- load + pack Q rows (lanes 0..12 handle c=lane) ----
    if (lane < 13) {
        const float2* qp = d_Q + (head * 13 + lane) * F + fbase;
        float2 a0 = (fbase + 0 < F) ? qp[0] : make_float2(0.f, 0.f);
        float2 a1 = (fbase + 1 < F) ? qp[1] : make_float2(0.f, 0.f);
        float2 a2 = (fbase + 2 < F) ? qp[2] : make_float2(0.f, 0.f);
        float2 a3 = (fbase + 3 < F) ? qp[3] : make_float2(0.f, 0.f);
        ull* dst = qpk + (w * 13 + lane) * 4;
        dst[0] = pk2(a0.x, a1.x);   // qx01
        dst[1] = pk2(a2.x, a3.x);   // qx23
        dst[2] = pk2(a0.y, a1.y);   // qy01
        dst[3] = pk2(a2.y, a3.y);   // qy23
    }

    // ---- fill kv with K (whole head), zero-pad cols 513..575 ----
    for (int i = tid; i < 13 * KPITCH; i += 256) {
        int c = i / KPITCH, f2 = i - c * KPITCH;
        kv[i] = (f2 < F) ? d_K[(head * 13 + c) * F + f2] : make_float2(0.f, 0.f);
    }
    __syncthreads();

    const ull Z = pk2(0.f, 0.f);
    float m0 = 0.f, m1 = 0.f, m2 = 0.f, m3 = 0.f;  // scores >= 0

    // ================= pass 1: scores -> d_S ==============================
#pragma unroll 1
    for (int cb = 0; cb < 576; cb += 64) {
        int col0 = cb + lane;
        int col1 = col0 + 32;
        ull Aa01 = Z, Aa23 = Z, Ba01 = Z, Ba23 = Z, Sa01 = Z, Sa23 = Z;
        ull Ab01 = Z, Ab23 = Z, Bb01 = Z, Bb23 = Z, Sb01 = Z, Sb23 = Z;
#pragma unroll
        for (int c = 0; c < 13; ++c) {
            const ulonglong2* qq = (const ulonglong2*)(qpk + (w * 13 + c) * 4);
            ulonglong2 t0 = qq[0];  // {qx01, qx23}
            ulonglong2 t1 = qq[1];  // {qy01, qy23}
            float2 k0 = kv[c * KPITCH + col0];
            float2 k1 = kv[c * KPITCH + col1];
            ull kxx = pk2(k0.x, k0.x), kyy = pk2(k0.y, k0.y);
            Aa01 = fma2(t0.x, kxx, Aa01);  Aa23 = fma2(t0.y, kxx, Aa23);
            Ba01 = fma2(t1.x, kyy, Ba01);  Ba23 = fma2(t1.y, kyy, Ba23);
            Sa01 = fma2(t0.x, kyy, Sa01);  Sa01 = fma2(t1.x, kxx, Sa01);
            Sa23 = fma2(t0.y, kyy, Sa23);  Sa23 = fma2(t1.y, kxx, Sa23);
            kxx = pk2(k1.x, k1.x);  kyy = pk2(k1.y, k1.y);
            Ab01 = fma2(t0.x, kxx, Ab01);  Ab23 = fma2(t0.y, kxx, Ab23);
            Bb01 = fma2(t1.x, kyy, Bb01);  Bb23 = fma2(t1.y, kyy, Bb23);
            Sb01 = fma2(t0.x, kyy, Sb01);  Sb01 = fma2(t1.x, kxx, Sb01);
            Sb23 = fma2(t0.y, kyy, Sb23);  Sb23 = fma2(t1.y, kxx, Sb23);
        }
        {
            float a0, a1, a2, a3, b0, b1, b2, b3, s0, s1, s2, s3;
            upk2(Aa01, a0, a1); upk2(Aa23, a2, a3);
            upk2(Ba01, b0, b1); upk2(Ba23, b2, b3);
            upk2(Sa01, s0, s1); upk2(Sa23, s2, s3);
            float sr0 = a0 - b0, sr1 = a1 - b1, sr2 = a2 - b2, sr3 = a3 - b3;
            float n0 = fmaf(sr0, sr0, s0 * s0);
            float n1 = fmaf(sr1, sr1, s1 * s1);
            float n2 = fmaf(sr2, sr2, s2 * s2);
            float n3 = fmaf(sr3, sr3, s3 * s3);
            float sc0 = n0 > 0.f ? n0 * __frsqrt_rn(n0) : 0.f;
            float sc1 = n1 > 0.f ? n1 * __frsqrt_rn(n1) : 0.f;
            float sc2 = n2 > 0.f ? n2 * __frsqrt_rn(n2) : 0.f;
            float sc3 = n3 > 0.f ? n3 * __frsqrt_rn(n3) : 0.f;
            m0 = fmaxf(m0, sc0); m1 = fmaxf(m1, sc1);
            m2 = fmaxf(m2, sc2); m3 = fmaxf(m3, sc3);
            if (col0 < F) srow[col0] = make_float4(sc0, sc1, sc2, sc3);
        }
        {
            float a0, a1, a2, a3, b0, b1, b2, b3, s0, s1, s2, s3;
            upk2(Ab01, a0, a1); upk2(Ab23, a2, a3);
            upk2(Bb01, b0, b1); upk2(Bb23, b2, b3);
            upk2(Sb01, s0, s1); upk2(Sb23, s2, s3);
            float sr0 = a0 - b0, sr1 = a1 - b1, sr2 = a2 - b2, sr3 = a3 - b3;
            float n0 = fmaf(sr0, sr0, s0 * s0);
            float n1 = fmaf(sr1, sr1, s1 * s1);
            float n2 = fmaf(sr2, sr2, s2 * s2);
            float n3 = fmaf(sr3, sr3, s3 * s3);
            float sc0 = n0 > 0.f ? n0 * __frsqrt_rn(n0) : 0.f;
            float sc1 = n1 > 0.f ? n1 * __frsqrt_rn(n1) : 0.f;
            float sc2 = n2 > 0.f ? n2 * __frsqrt_rn(n2) : 0.f;
            float sc3 = n3 > 0.f ? n3 * __frsqrt_rn(n3) : 0.f;
            m0 = fmaxf(m0, sc0); m1 = fmaxf(m1, sc1);
            m2 = fmaxf(m2, sc2); m3 = fmaxf(m3, sc3);
            if (col1 < F) srow[col1] = make_float4(sc0, sc1, sc2, sc3);
        }
    }

    // warp-reduce row maxima (kept in regs across passes)
#pragma unroll
    for (int o = 16; o; o >>= 1) {
        m0 = fmaxf(m0, __shfl_xor_sync(0xffffffffu, m0, o));
        m1 = fmaxf(m1, __shfl_xor_sync(0xffffffffu, m1, o));
        m2 = fmaxf(m2, __shfl_xor_sync(0xffffffffu, m2, o));
        m3 = fmaxf(m3, __shfl_xor_sync(0xffffffffu, m3, o));
    }

    // ---- swap kv to V ----
    __syncthreads();
    for (int i = tid; i < 13 * KPITCH; i += 256) {
        int c = i / KPITCH, f2 = i - c * KPITCH;
        kv[i] = (f2 < F) ? d_V[(head * 13 + c) * F + f2] : make_float2(0.f, 0.f);
    }
    __syncthreads();

    // ================= pass 2 (softmax fused): out = softmax(S) @ V =======
    float inv0 = 0.f, inv1 = 0.f, inv2 = 0.f, inv3 = 0.f;
#pragma unroll 1
    for (int h = 0; h < 2; ++h) {
        const int c0 = h ? 7 : 0;
        const int nc = h ? 6 : 7;
        ull ar01[7], ar23[7], ai01[7], ai23[7];
#pragma unroll
        for (int cc = 0; cc < 7; ++cc) { ar01[cc] = ar23[cc] = ai01[cc] = ai23[cc] = Z; }
        float l0 = 0.f, l1 = 0.f, l2 = 0.f, l3 = 0.f;

#pragma unroll 1
        for (int cb = 0; cb < 544; cb += 32) {
            int col = cb + lane;
            float4 s = (col < F) ? srow[col] : make_float4(-1e30f, -1e30f, -1e30f, -1e30f);
            float p0 = __expf(s.x - m0);
            float p1 = __expf(s.y - m1);
            float p2 = __expf(s.z - m2);
            float p3 = __expf(s.w - m3);
            if (h == 0) { l0 += p0; l1 += p1; l2 += p2; l3 += p3; }
            ull p01 = pk2(p0, p1), p23 = pk2(p2, p3);
#pragma unroll
            for (int cc = 0; cc < 7; ++cc) {
                if (cc < nc) {
                    float2 v = kv[(c0 + cc) * KPITCH + col];
                    ull vxx = pk2(v.x, v.x), vyy = pk2(v.y, v.y);
                    ar01[cc] = fma2(p01, vxx, ar01[cc]);
                    ar23[cc] = fma2(p23, vxx, ar23[cc]);
                    ai01[cc] = fma2(p01, vyy, ai01[cc]);
                    ai23[cc] = fma2(p23, vyy, ai23[cc]);
                }
            }
        }

        if (h == 0) {
#pragma unroll
            for (int o = 16; o; o >>= 1) {
                l0 += __shfl_xor_sync(0xffffffffu, l0, o);
                l1 += __shfl_xor_sync(0xffffffffu, l1, o);
                l2 += __shfl_xor_sync(0xffffffffu, l2, o);
                l3 += __shfl_xor_sync(0xffffffffu, l3, o);
            }
            inv0 = 1.f / l0; inv1 = 1.f / l1; inv2 = 1.f / l2; inv3 = 1.f / l3;
        }

        for (int cc = 0; cc < nc; ++cc) {
            float r0, r1, r2, r3, i0, i1, i2, i3;
            upk2(ar01[cc], r0, r1); upk2(ar23[cc], r2, r3);
            upk2(ai01[cc], i0, i1); upk2(ai23[cc], i2, i3);
#pragma unroll
            for (int o = 16; o; o >>= 1) {
                r0 += __shfl_xor_sync(0xffffffffu, r0, o);
                r1 += __shfl_xor_sync(0xffffffffu, r1, o);
                r2 += __shfl_xor_sync(0xffffffffu, r2, o);
                r3 += __shfl_xor_sync(0xffffffffu, r3, o);
                i0 += __shfl_xor_sync(0xffffffffu, i0, o);
                i1 += __shfl_xor_sync(0xffffffffu, i1, o);
                i2 += __shfl_xor_sync(0xffffffffu, i2, o);
                i3 += __shfl_xor_sync(0xffffffffu, i3, o);
            }
            if (lane == 0) {
                float2* op = d_O + (head * 13 + c0 + cc) * F + fbase;
                if (fbase + 0 < F) op[0] = make_float2(r0 * inv0, i0 * inv0);
                if (fbase + 1 < F) op[1] = make_float2(r1 * inv1, i1 * inv1);
                if (fbase + 2 < F) op[2] = make_float2(r2 * inv2, i2 * inv2);
                if (fbase + 3 < F) op[3] = make_float2(r3 * inv3, i3 * inv3);
            }
        }
    }
}

// ---------------- irfft: Hermitian extend + inverse FFT, real part ---------
__global__ void ifft_kernel(float* __restrict__ out) {
    __shared__ float2 a[1024];
    int sig = blockIdx.x;
    int tid = threadIdx.x;  // 0..511
    const float2* Op = d_O + sig * F;
    float2 o = Op[tid];
    a[__brev(tid) >> 22] = o;
    if (tid > 0) a[__brev(1024 - tid) >> 22] = make_float2(o.x, -o.y);
    if (tid == 0) a[__brev(512) >> 22] = Op[512];
    fft_stages(a, true);
    const float scale = 1.0f / 1024.0f;
    float* op = out + sig * 1024;
    op[tid]       = a[tid].x * scale;
    op[tid + 512] = a[tid + 512].x * scale;
}

// ---------------- launcher --------------------------------------------------
extern "C" void kernel_launch(void* const* d_in, const int* in_sizes, int n_in,
                              void* d_out, int out_size) {
    const float* x  = (const float*)d_in[0];
    const float* wq = (const float*)d_in[1];
    const float* wk = (const float*)d_in[2];
    const float* wv = (const float*)d_in[3];
    float* out = (float*)d_out;

    cudaFuncSetAttribute(attn_kernel, cudaFuncAttributeMaxDynamicSharedMemorySize, SM_TOTAL);

    init_twiddles<<<1, 512>>>();
    fft_forward<<<NSIG, 512>>>(x);
    qkv_kernel<<<dim3(3, H), 256>>>(wq, wk, wv);
    attn_kernel<<<dim3((F + TRR - 1) / TRR, H), 256, SM_TOTAL>>>();
    ifft_kernel<<<NSIG, 512>>>(out);
}

// round 9
// speedup vs baseline: 1.2923x; 1.2923x over previous
#include <cuda_runtime.h>
#include <math.h>

#define H 160           // B*G = 4*40 heads
#define C 13
#define T 1024
#define F 513           // rfft bins
#define NSIG (H * C)    // 2080 signals

typedef unsigned long long ull;

// ---------------- f32x2 packed math helpers (sm_103a FFMA2) ----------------
__device__ __forceinline__ ull pk2(float a, float b) {
    ull r;
    asm("mov.b64 %0, {%1, %2};" : "=l"(r) : "r"(__float_as_uint(a)), "r"(__float_as_uint(b)));
    return r;
}
__device__ __forceinline__ void upk2(ull v, float& a, float& b) {
    unsigned lo, hi;
    asm("mov.b64 {%0, %1}, %2;" : "=r"(lo), "=r"(hi) : "l"(v));
    a = __uint_as_float(lo);
    b = __uint_as_float(hi);
}
__device__ __forceinline__ ull fma2(ull a, ull b, ull c) {
    ull d;
    asm("fma.rn.f32x2 %0, %1, %2, %3;" : "=l"(d) : "l"(a), "l"(b), "l"(c));
    return d;
}

// ---------------- scratch (device globals: allowed; no runtime alloc) ------
__device__ float2 d_W[512];        // twiddles exp(-2*pi*i*k/1024)
__device__ float2 d_X[H * C * F];  // spectrum, layout [head][c][f]
__device__ float2 d_Q[H * C * F];
__device__ float2 d_K[H * C * F];
__device__ float2 d_V[H * C * F];
__device__ float2 d_O[H * C * F];

// flash partials: [head][rowgroup 136][split 5][28 float4]
//   float4 0..25: acc (c*2 = real rows0-3, c*2+1 = imag rows0-3)
//   float4 26: m per row, float4 27: l per row
#define NRG 136
#define NSPLIT 5
#define KT 104
#define KTP 128
__device__ float4 d_P[(size_t)H * NRG * NSPLIT * 28];   // ~48.7 MB

// ---------------- twiddle init (double trig for precision) -----------------
__global__ void init_twiddles() {
    int k = threadIdx.x;  // 0..511
    double ang = -2.0 * 3.14159265358979323846 * (double)k / 1024.0;
    d_W[k] = make_float2((float)cos(ang), (float)sin(ang));
}

// ---------------- shared radix-2 DIT FFT core (1024 pts, 512 threads) ------
__device__ __forceinline__ void fft_stages(float2* a, bool inverse) {
    int tid = threadIdx.x;
#pragma unroll
    for (int s = 1; s <= 10; ++s) {
        __syncthreads();
        int half = 1 << (s - 1);
        int k = tid & (half - 1);
        int i0 = ((tid >> (s - 1)) << s) + k;
        float2 w = d_W[k << (10 - s)];
        if (inverse) w.y = -w.y;
        float2 u = a[i0];
        float2 v = a[i0 + half];
        float tr = w.x * v.x - w.y * v.y;
        float ti = w.x * v.y + w.y * v.x;
        a[i0]        = make_float2(u.x + tr, u.y + ti);
        a[i0 + half] = make_float2(u.x - tr, u.y - ti);
    }
    __syncthreads();
}

// ---------------- forward rfft: x[sig][0..1023] -> d_X[sig][0..512] --------
__global__ void fft_forward(const float* __restrict__ x) {
    __shared__ float2 a[1024];
    int sig = blockIdx.x;   // head*13 + c
    int tid = threadIdx.x;  // 0..511
    const float* xp = x + sig * 1024;
    a[__brev(tid) >> 22]       = make_float2(xp[tid], 0.f);
    a[__brev(tid + 512) >> 22] = make_float2(xp[tid + 512], 0.f);
    fft_stages(a, false);
    float2* Xp = d_X + sig * F;
    Xp[tid] = a[tid];
    if (tid == 0) Xp[512] = a[512];
}

// ---------------- QKV: [head][c][f] = sum_cin X[head][cin][f] * W[cin][c] --
__global__ void qkv_kernel(const float* __restrict__ wq,
                           const float* __restrict__ wk,
                           const float* __restrict__ wv) {
    __shared__ float ws[3][169];
    int tid = threadIdx.x;
    if (tid < 169) {
        ws[0][tid] = wq[tid];
        ws[1][tid] = wk[tid];
        ws[2][tid] = wv[tid];
    }
    __syncthreads();
    int head = blockIdx.y;
    int f = blockIdx.x * blockDim.x + tid;
    if (f >= F) return;
    float xr[13], xi[13];
#pragma unroll
    for (int c = 0; c < 13; ++c) {
        float2 v = d_X[(head * 13 + c) * F + f];
        xr[c] = v.x;
        xi[c] = v.y;
    }
#pragma unroll 1
    for (int co = 0; co < 13; ++co) {
        float qr = 0.f, qi = 0.f, kr = 0.f, ki = 0.f, vr = 0.f, vi = 0.f;
#pragma unroll
        for (int ci = 0; ci < 13; ++ci) {
            float a = ws[0][ci * 13 + co];
            qr = fmaf(xr[ci], a, qr); qi = fmaf(xi[ci], a, qi);
            float b = ws[1][ci * 13 + co];
            kr = fmaf(xr[ci], b, kr); ki = fmaf(xi[ci], b, ki);
            float g = ws[2][ci * 13 + co];
            vr = fmaf(xr[ci], g, vr); vi = fmaf(xi[ci], g, vi);
        }
        int o = (head * 13 + co) * F + f;
        d_Q[o] = make_float2(qr, qi);
        d_K[o] = make_float2(kr, ki);
        d_V[o] = make_float2(vr, vi);
    }
}

// ---------------- attention (split-column flash, no score memory) ----------
// CTA = 32 rows x 104 cols of one head. 8 warps x 4 rows/warp.
// Scores live entirely in registers (4 cols x 4 rows per lane, f32x2-packed).
// Split-local softmax partials (m, l, P.V) written to d_P; combine_kernel
// merges the 5 column splits. ONE __syncthreads in the whole kernel.
__global__ __launch_bounds__(256, 3) void attn_kernel() {
    __shared__ float2 ksm[13 * KTP];   // 13312 B
    __shared__ float2 vsm[13 * KTP];   // 13312 B
    __shared__ ull    qpk[8 * 13 * 6]; //  4992 B  (qx01,qx23,qy01,qy23,-qy01,-qy23)

    int head = blockIdx.y;
    int rb = blockIdx.x / NSPLIT;
    int split = blockIdx.x - rb * NSPLIT;
    int tid = threadIdx.x, lane = tid & 31, w = tid >> 5;
    int fbase = rb * 32 + 4 * w;
    int colbase = split * KT;

    // pack Q rows fbase..fbase+3 (lanes 0..12 handle c=lane)
    if (lane < 13) {
        const float2* qp = d_Q + (head * 13 + lane) * F + fbase;
        float2 a0 = (fbase + 0 < F) ? qp[0] : make_float2(0.f, 0.f);
        float2 a1 = (fbase + 1 < F) ? qp[1] : make_float2(0.f, 0.f);
        float2 a2 = (fbase + 2 < F) ? qp[2] : make_float2(0.f, 0.f);
        float2 a3 = (fbase + 3 < F) ? qp[3] : make_float2(0.f, 0.f);
        ull* dst = qpk + (w * 13 + lane) * 6;
        dst[0] = pk2(a0.x, a1.x);   dst[1] = pk2(a2.x, a3.x);
        dst[2] = pk2(a0.y, a1.y);   dst[3] = pk2(a2.y, a3.y);
        dst[4] = pk2(-a0.y, -a1.y); dst[5] = pk2(-a2.y, -a3.y);
    }
    // load K,V tile (cols colbase..colbase+103, zero-pad to 128)
    for (int i = tid; i < 13 * KTP; i += 256) {
        int c = i >> 7, fl = i & 127;
        int f2 = colbase + fl;
        bool ok = (fl < KT) && (f2 < F);
        float2 kv = ok ? d_K[(head * 13 + c) * F + f2] : make_float2(0.f, 0.f);
        float2 vv = ok ? d_V[(head * 13 + c) * F + f2] : make_float2(0.f, 0.f);
        ksm[i] = kv;
        vsm[i] = vv;
    }
    __syncthreads();

    const ull Z = pk2(0.f, 0.f);
    ull sr01[4], sr23[4], si01[4], si23[4];
#pragma unroll
    for (int j = 0; j < 4; ++j) { sr01[j] = sr23[j] = si01[j] = si23[j] = Z; }

    // ---- pass 1: complex dot products (c outer, 4 cols inner) ----
#pragma unroll 1
    for (int c = 0; c < 13; ++c) {
        const ulonglong2* qq = (const ulonglong2*)(qpk + (w * 13 + c) * 6);
        ulonglong2 tx = qq[0];  // {qx01, qx23}
        ulonglong2 ty = qq[1];  // {qy01, qy23}
        ulonglong2 tn = qq[2];  // {-qy01,-qy23}
#pragma unroll
        for (int j = 0; j < 4; ++j) {
            float2 k = ksm[c * KTP + j * 32 + lane];
            ull kxx = pk2(k.x, k.x), kyy = pk2(k.y, k.y);
            sr01[j] = fma2(tx.x, kxx, sr01[j]);  sr01[j] = fma2(tn.x, kyy, sr01[j]);
            sr23[j] = fma2(tx.y, kxx, sr23[j]);  sr23[j] = fma2(tn.y, kyy, sr23[j]);
            si01[j] = fma2(tx.x, kyy, si01[j]);  si01[j] = fma2(ty.x, kxx, si01[j]);
            si23[j] = fma2(tx.y, kyy, si23[j]);  si23[j] = fma2(ty.y, kxx, si23[j]);
        }
    }

    // ---- magnitudes -> scores (packed back into sr01/sr23), per-lane max --
    float m0 = 0.f, m1 = 0.f, m2 = 0.f, m3 = 0.f;
#pragma unroll
    for (int j = 0; j < 4; ++j) {
        float r0, r1, r2, r3, u0, u1, u2, u3;
        upk2(sr01[j], r0, r1); upk2(sr23[j], r2, r3);
        upk2(si01[j], u0, u1); upk2(si23[j], u2, u3);
        float n0 = fmaf(r0, r0, u0 * u0);
        float n1 = fmaf(r1, r1, u1 * u1);
        float n2 = fmaf(r2, r2, u2 * u2);
        float n3 = fmaf(r3, r3, u3 * u3);
        float sc0 = n0 > 0.f ? n0 * __frsqrt_rn(n0) : 0.f;
        float sc1 = n1 > 0.f ? n1 * __frsqrt_rn(n1) : 0.f;
        float sc2 = n2 > 0.f ? n2 * __frsqrt_rn(n2) : 0.f;
        float sc3 = n3 > 0.f ? n3 * __frsqrt_rn(n3) : 0.f;
        m0 = fmaxf(m0, sc0); m1 = fmaxf(m1, sc1);
        m2 = fmaxf(m2, sc2); m3 = fmaxf(m3, sc3);
        sr01[j] = pk2(sc0, sc1); sr23[j] = pk2(sc2, sc3);
    }
    // warp-reduce split-local row maxima
#pragma unroll
    for (int o = 16; o; o >>= 1) {
        m0 = fmaxf(m0, __shfl_xor_sync(0xffffffffu, m0, o));
        m1 = fmaxf(m1, __shfl_xor_sync(0xffffffffu, m1, o));
        m2 = fmaxf(m2, __shfl_xor_sync(0xffffffffu, m2, o));
        m3 = fmaxf(m3, __shfl_xor_sync(0xffffffffu, m3, o));
    }

    // ---- p = exp(s - m) (masked), l accumulation ----
    float l0 = 0.f, l1 = 0.f, l2 = 0.f, l3 = 0.f;
#pragma unroll
    for (int j = 0; j < 4; ++j) {
        int col = j * 32 + lane;
        bool valid = (col < KT) && (colbase + col < F);
        float s0, s1, s2, s3;
        upk2(sr01[j], s0, s1); upk2(sr23[j], s2, s3);
        float p0 = valid ? __expf(s0 - m0) : 0.f;
        float p1 = valid ? __expf(s1 - m1) : 0.f;
        float p2 = valid ? __expf(s2 - m2) : 0.f;
        float p3 = valid ? __expf(s3 - m3) : 0.f;
        l0 += p0; l1 += p1; l2 += p2; l3 += p3;
        sr01[j] = pk2(p0, p1); sr23[j] = pk2(p2, p3);
    }
#pragma unroll
    for (int o = 16; o; o >>= 1) {
        l0 += __shfl_xor_sync(0xffffffffu, l0, o);
        l1 += __shfl_xor_sync(0xffffffffu, l1, o);
        l2 += __shfl_xor_sync(0xffffffffu, l2, o);
        l3 += __shfl_xor_sync(0xffffffffu, l3, o);
    }

    size_t pb = ((size_t)(head * NRG + rb * 8 + w) * NSPLIT + split) * 28;
    if (lane == 0) {
        d_P[pb + 26] = make_float4(m0, m1, m2, m3);
        d_P[pb + 27] = make_float4(l0, l1, l2, l3);
    }

    // ---- pass 2: partial P @ V per c, reduce, write ----
#pragma unroll 1
    for (int c = 0; c < 13; ++c) {
        ull ar01 = Z, ar23 = Z, ai01 = Z, ai23 = Z;
#pragma unroll
        for (int j = 0; j < 4; ++j) {
            float2 v = vsm[c * KTP + j * 32 + lane];
            ull vxx = pk2(v.x, v.x), vyy = pk2(v.y, v.y);
            ar01 = fma2(sr01[j], vxx, ar01);  ar23 = fma2(sr23[j], vxx, ar23);
            ai01 = fma2(sr01[j], vyy, ai01);  ai23 = fma2(sr23[j], vyy, ai23);
        }
        float r0, r1, r2, r3, u0, u1, u2, u3;
        upk2(ar01, r0, r1); upk2(ar23, r2, r3);
        upk2(ai01, u0, u1); upk2(ai23, u2, u3);
#pragma unroll
        for (int o = 16; o; o >>= 1) {
            r0 += __shfl_xor_sync(0xffffffffu, r0, o);
            r1 += __shfl_xor_sync(0xffffffffu, r1, o);
            r2 += __shfl_xor_sync(0xffffffffu, r2, o);
            r3 += __shfl_xor_sync(0xffffffffu, r3, o);
            u0 += __shfl_xor_sync(0xffffffffu, u0, o);
            u1 += __shfl_xor_sync(0xffffffffu, u1, o);
            u2 += __shfl_xor_sync(0xffffffffu, u2, o);
            u3 += __shfl_xor_sync(0xffffffffu, u3, o);
        }
        if (lane == 0) {
            d_P[pb + c * 2 + 0] = make_float4(r0, r1, r2, r3);
            d_P[pb + c * 2 + 1] = make_float4(u0, u1, u2, u3);
        }
    }
}

// ---------------- combine: merge 5 column-split partials -------------------
// block = 128 threads (104 active) per (rowgroup, head); thread handles one
// output float (row, c, re/im).
__global__ void combine_kernel() {
    int rg = blockIdx.x;       // 0..135
    int head = blockIdx.y;
    int t = threadIdx.x;
    if (t >= 104) return;
    int c = t >> 3;
    int comp = t & 7;
    int row = comp & 3, isim = comp >> 2;

    const float* P = (const float*)(d_P + (size_t)(head * NRG + rg) * NSPLIT * 28);
    // per split: 28 float4 = 112 floats. m at 104+row, l at 108+row.
    float M = -1e30f;
#pragma unroll
    for (int k = 0; k < NSPLIT; ++k) M = fmaxf(M, P[k * 112 + 104 + row]);
    float L = 0.f, val = 0.f;
#pragma unroll
    for (int k = 0; k < NSPLIT; ++k) {
        float mk = P[k * 112 + 104 + row];
        float lk = P[k * 112 + 108 + row];
        float s = __expf(mk - M);
        L += lk * s;
        val = fmaf(P[k * 112 + (c * 2 + isim) * 4 + row], s, val);
    }
    int f = rg * 4 + row;
    if (f < F)
        ((float*)d_O)[(size_t)((head * 13 + c) * F + f) * 2 + isim] = val / L;
}

// ---------------- irfft: Hermitian extend + inverse FFT, real part ---------
__global__ void ifft_kernel(float* __restrict__ out) {
    __shared__ float2 a[1024];
    int sig = blockIdx.x;
    int tid = threadIdx.x;  // 0..511
    const float2* Op = d_O + sig * F;
    float2 o = Op[tid];
    a[__brev(tid) >> 22] = o;
    if (tid > 0) a[__brev(1024 - tid) >> 22] = make_float2(o.x, -o.y);
    if (tid == 0) a[__brev(512) >> 22] = Op[512];
    fft_stages(a, true);
    const float scale = 1.0f / 1024.0f;
    float* op = out + sig * 1024;
    op[tid]       = a[tid].x * scale;
    op[tid + 512] = a[tid + 512].x * scale;
}

// ---------------- launcher --------------------------------------------------
extern "C" void kernel_launch(void* const* d_in, const int* in_sizes, int n_in,
                              void* d_out, int out_size) {
    const float* x  = (const float*)d_in[0];
    const float* wq = (const float*)d_in[1];
    const float* wk = (const float*)d_in[2];
    const float* wv = (const float*)d_in[3];
    float* out = (float*)d_out;

    init_twiddles<<<1, 512>>>();
    fft_forward<<<NSIG, 512>>>(x);
    qkv_kernel<<<dim3(3, H), 256>>>(wq, wk, wv);
    attn_kernel<<<dim3(17 * NSPLIT, H), 256>>>();
    combine_kernel<<<dim3(NRG, H), 128>>>();
    ifft_kernel<<<NSIG, 512>>>(out);
}

// round 10
// speedup vs baseline: 1.3995x; 1.0830x over previous
#include <cuda_runtime.h>
#include <math.h>

#define H 160           // B*G = 4*40 heads
#define C 13
#define T 1024
#define F 513           // rfft bins
#define NSIG (H * C)    // 2080 signals

typedef unsigned long long ull;

// ---------------- f32x2 packed math helpers (sm_103a FFMA2) ----------------
__device__ __forceinline__ ull pk2(float a, float b) {
    ull r;
    asm("mov.b64 %0, {%1, %2};" : "=l"(r) : "r"(__float_as_uint(a)), "r"(__float_as_uint(b)));
    return r;
}
__device__ __forceinline__ void upk2(ull v, float& a, float& b) {
    unsigned lo, hi;
    asm("mov.b64 {%0, %1}, %2;" : "=r"(lo), "=r"(hi) : "l"(v));
    a = __uint_as_float(lo);
    b = __uint_as_float(hi);
}
__device__ __forceinline__ ull fma2(ull a, ull b, ull c) {
    ull d;
    asm("fma.rn.f32x2 %0, %1, %2, %3;" : "=l"(d) : "l"(a), "l"(b), "l"(c));
    return d;
}
__device__ __forceinline__ ull add2(ull a, ull b) {
    ull d;
    asm("add.rn.f32x2 %0, %1, %2;" : "=l"(d) : "l"(a), "l"(b));
    return d;
}
__device__ __forceinline__ ull shfl_xor_ull(ull v, int m) {
    unsigned lo, hi;
    asm("mov.b64 {%0, %1}, %2;" : "=r"(lo), "=r"(hi) : "l"(v));
    lo = __shfl_xor_sync(0xffffffffu, lo, m);
    hi = __shfl_xor_sync(0xffffffffu, hi, m);
    ull r;
    asm("mov.b64 %0, {%1, %2};" : "=l"(r) : "r"(lo), "r"(hi));
    return r;
}

// ---------------- scratch (device globals: allowed; no runtime alloc) ------
__device__ float2 d_W[512];        // twiddles exp(-2*pi*i*k/1024)
__device__ float2 d_X[H * C * F];  // spectrum, layout [head][c][f]
__device__ float2 d_Q[H * C * F];
__device__ float2 d_K[H * C * F];
__device__ float2 d_V[H * C * F];
__device__ float2 d_O[H * C * F];

// flash partials, ull-packed. Per (head, rowgroup, split) record = 56 ull:
//   c*4 + u, u = 0:{r0,r1} 1:{i0,i1} 2:{r2,r3} 3:{i2,i3}    (c = 0..12)
//   52:{m0,m1} 53:{m2,m3} 54:{l0,l1} 55:{l2,l3}
#define NRG 136        // 17 row-blocks * 8 warps (4 rows each)
#define NSPLIT 5
#define KT 104
#define KTP 128
__device__ ull d_P[(size_t)H * NRG * NSPLIT * 56];   // ~48.7 MB

// ---------------- twiddle init (double trig for precision) -----------------
__global__ void init_twiddles() {
    int k = threadIdx.x;  // 0..511
    double ang = -2.0 * 3.14159265358979323846 * (double)k / 1024.0;
    d_W[k] = make_float2((float)cos(ang), (float)sin(ang));
}

// ---------------- shared radix-2 DIT FFT core (1024 pts, 512 threads) ------
__device__ __forceinline__ void fft_stages(float2* a, bool inverse) {
    int tid = threadIdx.x;
#pragma unroll
    for (int s = 1; s <= 10; ++s) {
        __syncthreads();
        int half = 1 << (s - 1);
        int k = tid & (half - 1);
        int i0 = ((tid >> (s - 1)) << s) + k;
        float2 w = d_W[k << (10 - s)];
        if (inverse) w.y = -w.y;
        float2 u = a[i0];
        float2 v = a[i0 + half];
        float tr = w.x * v.x - w.y * v.y;
        float ti = w.x * v.y + w.y * v.x;
        a[i0]        = make_float2(u.x + tr, u.y + ti);
        a[i0 + half] = make_float2(u.x - tr, u.y - ti);
    }
    __syncthreads();
}

// ---------------- forward rfft: x[sig][0..1023] -> d_X[sig][0..512] --------
__global__ void fft_forward(const float* __restrict__ x) {
    __shared__ float2 a[1024];
    int sig = blockIdx.x;   // head*13 + c
    int tid = threadIdx.x;  // 0..511
    const float* xp = x + sig * 1024;
    a[__brev(tid) >> 22]       = make_float2(xp[tid], 0.f);
    a[__brev(tid + 512) >> 22] = make_float2(xp[tid + 512], 0.f);
    fft_stages(a, false);
    float2* Xp = d_X + sig * F;
    Xp[tid] = a[tid];
    if (tid == 0) Xp[512] = a[512];
}

// ---------------- QKV: [head][c][f] = sum_cin X[head][cin][f] * W[cin][c] --
__global__ void qkv_kernel(const float* __restrict__ wq,
                           const float* __restrict__ wk,
                           const float* __restrict__ wv) {
    __shared__ float ws[3][169];
    int tid = threadIdx.x;
    if (tid < 169) {
        ws[0][tid] = wq[tid];
        ws[1][tid] = wk[tid];
        ws[2][tid] = wv[tid];
    }
    __syncthreads();
    int head = blockIdx.y;
    int f = blockIdx.x * blockDim.x + tid;
    if (f >= F) return;
    float xr[13], xi[13];
#pragma unroll
    for (int c = 0; c < 13; ++c) {
        float2 v = d_X[(head * 13 + c) * F + f];
        xr[c] = v.x;
        xi[c] = v.y;
    }
#pragma unroll 1
    for (int co = 0; co < 13; ++co) {
        float qr = 0.f, qi = 0.f, kr = 0.f, ki = 0.f, vr = 0.f, vi = 0.f;
#pragma unroll
        for (int ci = 0; ci < 13; ++ci) {
            float a = ws[0][ci * 13 + co];
            qr = fmaf(xr[ci], a, qr); qi = fmaf(xi[ci], a, qi);
            float b = ws[1][ci * 13 + co];
            kr = fmaf(xr[ci], b, kr); ki = fmaf(xi[ci], b, ki);
            float g = ws[2][ci * 13 + co];
            vr = fmaf(xr[ci], g, vr); vi = fmaf(xi[ci], g, vi);
        }
        int o = (head * 13 + co) * F + f;
        d_Q[o] = make_float2(qr, qi);
        d_K[o] = make_float2(kr, ki);
        d_V[o] = make_float2(vr, vi);
    }
}

// ---------------- attention (split-column flash, register scores) ----------
// CTA = 32 rows x 104 cols of one head; 8 warps x 4 rows/warp.
// Lane owns 4 CONTIGUOUS cols (4*lane+j) -> K/V via LDS.128 pairs.
// Pass-2 lane reduction = value-halving butterfly (12 shfl.b32 per c vs 40).
__global__ __launch_bounds__(256, 3) void attn_kernel() {
    __shared__ __align__(16) float2 ksm[13 * KTP];   // 13312 B
    __shared__ __align__(16) float2 vsm[13 * KTP];   // 13312 B
    __shared__ __align__(16) ull    qpk[8 * 13 * 6]; //  4992 B

    int head = blockIdx.y;
    int rb = blockIdx.x / NSPLIT;
    int split = blockIdx.x - rb * NSPLIT;
    int tid = threadIdx.x, lane = tid & 31, w = tid >> 5;
    int fbase = rb * 32 + 4 * w;
    int colbase = split * KT;

    // pack Q rows fbase..fbase+3 (lanes 0..12 handle c=lane)
    if (lane < 13) {
        const float2* qp = d_Q + (head * 13 + lane) * F + fbase;
        float2 a0 = (fbase + 0 < F) ? qp[0] : make_float2(0.f, 0.f);
        float2 a1 = (fbase + 1 < F) ? qp[1] : make_float2(0.f, 0.f);
        float2 a2 = (fbase + 2 < F) ? qp[2] : make_float2(0.f, 0.f);
        float2 a3 = (fbase + 3 < F) ? qp[3] : make_float2(0.f, 0.f);
        ull* dst = qpk + (w * 13 + lane) * 6;
        dst[0] = pk2(a0.x, a1.x);   dst[1] = pk2(a2.x, a3.x);
        dst[2] = pk2(a0.y, a1.y);   dst[3] = pk2(a2.y, a3.y);
        dst[4] = pk2(-a0.y, -a1.y); dst[5] = pk2(-a2.y, -a3.y);
    }
    // load K,V tile (cols colbase..colbase+103, zero-pad to 128)
    for (int i = tid; i < 13 * KTP; i += 256) {
        int c = i >> 7, fl = i & 127;
        int f2 = colbase + fl;
        bool ok = (fl < KT) && (f2 < F);
        ksm[i] = ok ? d_K[(head * 13 + c) * F + f2] : make_float2(0.f, 0.f);
        vsm[i] = ok ? d_V[(head * 13 + c) * F + f2] : make_float2(0.f, 0.f);
    }
    __syncthreads();

    const ull Z = pk2(0.f, 0.f);
    ull sr01[4], sr23[4], si01[4], si23[4];
#pragma unroll
    for (int j = 0; j < 4; ++j) { sr01[j] = sr23[j] = si01[j] = si23[j] = Z; }

    // ---- pass 1: complex dot products (c outer, 4 contiguous cols/lane) ---
#pragma unroll 1
    for (int c = 0; c < 13; ++c) {
        const ulonglong2* qq = (const ulonglong2*)(qpk + (w * 13 + c) * 6);
        ulonglong2 tx = qq[0];  // {qx01, qx23}
        ulonglong2 ty = qq[1];  // {qy01, qy23}
        ulonglong2 tn = qq[2];  // {-qy01,-qy23}
        const float4* kp = (const float4*)(ksm + c * KTP + 4 * lane);
        float4 kA = kp[0];   // cols 4lane+0, 4lane+1
        float4 kB = kp[1];   // cols 4lane+2, 4lane+3
        float2 k[4] = { make_float2(kA.x, kA.y), make_float2(kA.z, kA.w),
                        make_float2(kB.x, kB.y), make_float2(kB.z, kB.w) };
#pragma unroll
        for (int j = 0; j < 4; ++j) {
            ull kxx = pk2(k[j].x, k[j].x), kyy = pk2(k[j].y, k[j].y);
            sr01[j] = fma2(tx.x, kxx, sr01[j]);  sr01[j] = fma2(tn.x, kyy, sr01[j]);
            sr23[j] = fma2(tx.y, kxx, sr23[j]);  sr23[j] = fma2(tn.y, kyy, sr23[j]);
            si01[j] = fma2(tx.x, kyy, si01[j]);  si01[j] = fma2(ty.x, kxx, si01[j]);
            si23[j] = fma2(tx.y, kyy, si23[j]);  si23[j] = fma2(ty.y, kxx, si23[j]);
        }
    }

    // ---- magnitudes -> scores (repacked into sr01/sr23), per-lane max -----
    float m0 = 0.f, m1 = 0.f, m2 = 0.f, m3 = 0.f;
#pragma unroll
    for (int j = 0; j < 4; ++j) {
        float r0, r1, r2, r3, u0, u1, u2, u3;
        upk2(sr01[j], r0, r1); upk2(sr23[j], r2, r3);
        upk2(si01[j], u0, u1); upk2(si23[j], u2, u3);
        float n0 = fmaf(r0, r0, u0 * u0);
        float n1 = fmaf(r1, r1, u1 * u1);
        float n2 = fmaf(r2, r2, u2 * u2);
        float n3 = fmaf(r3, r3, u3 * u3);
        float sc0 = n0 > 0.f ? n0 * __frsqrt_rn(n0) : 0.f;
        float sc1 = n1 > 0.f ? n1 * __frsqrt_rn(n1) : 0.f;
        float sc2 = n2 > 0.f ? n2 * __frsqrt_rn(n2) : 0.f;
        float sc3 = n3 > 0.f ? n3 * __frsqrt_rn(n3) : 0.f;
        m0 = fmaxf(m0, sc0); m1 = fmaxf(m1, sc1);
        m2 = fmaxf(m2, sc2); m3 = fmaxf(m3, sc3);
        sr01[j] = pk2(sc0, sc1); sr23[j] = pk2(sc2, sc3);
    }
#pragma unroll
    for (int o = 16; o; o >>= 1) {
        m0 = fmaxf(m0, __shfl_xor_sync(0xffffffffu, m0, o));
        m1 = fmaxf(m1, __shfl_xor_sync(0xffffffffu, m1, o));
        m2 = fmaxf(m2, __shfl_xor_sync(0xffffffffu, m2, o));
        m3 = fmaxf(m3, __shfl_xor_sync(0xffffffffu, m3, o));
    }

    // ---- p = exp(s - m) (masked), l accumulation --------------------------
    float l0 = 0.f, l1 = 0.f, l2 = 0.f, l3 = 0.f;
#pragma unroll
    for (int j = 0; j < 4; ++j) {
        int cl = 4 * lane + j;
        bool valid = (cl < KT) && (colbase + cl < F);
        float s0, s1, s2, s3;
        upk2(sr01[j], s0, s1); upk2(sr23[j], s2, s3);
        float p0 = valid ? __expf(s0 - m0) : 0.f;
        float p1 = valid ? __expf(s1 - m1) : 0.f;
        float p2 = valid ? __expf(s2 - m2) : 0.f;
        float p3 = valid ? __expf(s3 - m3) : 0.f;
        l0 += p0; l1 += p1; l2 += p2; l3 += p3;
        sr01[j] = pk2(p0, p1); sr23[j] = pk2(p2, p3);
    }
#pragma unroll
    for (int o = 16; o; o >>= 1) {
        l0 += __shfl_xor_sync(0xffffffffu, l0, o);
        l1 += __shfl_xor_sync(0xffffffffu, l1, o);
        l2 += __shfl_xor_sync(0xffffffffu, l2, o);
        l3 += __shfl_xor_sync(0xffffffffu, l3, o);
    }

    size_t pb = ((size_t)(head * NRG + rb * 8 + w) * NSPLIT + split) * 56;
    if (lane == 0) {
        d_P[pb + 52] = pk2(m0, m1);
        d_P[pb + 53] = pk2(m2, m3);
        d_P[pb + 54] = pk2(l0, l1);
        d_P[pb + 55] = pk2(l2, l3);
    }

    // ---- pass 2: partial P @ V per c; value-halving butterfly reduce ------
    bool hi16 = (lane & 16) != 0;
    bool hi8  = (lane & 8) != 0;
#pragma unroll 1
    for (int c = 0; c < 13; ++c) {
        ull ar01 = Z, ar23 = Z, ai01 = Z, ai23 = Z;
        const float4* vp = (const float4*)(vsm + c * KTP + 4 * lane);
        float4 vA = vp[0];
        float4 vB = vp[1];
        float2 v[4] = { make_float2(vA.x, vA.y), make_float2(vA.z, vA.w),
                        make_float2(vB.x, vB.y), make_float2(vB.z, vB.w) };
#pragma unroll
        for (int j = 0; j < 4; ++j) {
            ull vxx = pk2(v[j].x, v[j].x), vyy = pk2(v[j].y, v[j].y);
            ar01 = fma2(sr01[j], vxx, ar01);  ar23 = fma2(sr23[j], vxx, ar23);
            ai01 = fma2(sr01[j], vyy, ai01);  ai23 = fma2(sr23[j], vyy, ai23);
        }
        // stage 1 (xor16): lo keeps rows01, hi keeps rows23
        ull k0 = hi16 ? ar23 : ar01;   // keep re
        ull k1 = hi16 ? ai23 : ai01;   // keep im
        ull g0 = hi16 ? ar01 : ar23;   // give re
        ull g1 = hi16 ? ai01 : ai23;   // give im
        k0 = add2(k0, shfl_xor_ull(g0, 16));
        k1 = add2(k1, shfl_xor_ull(g1, 16));
        // stage 2 (xor8): lo8 keeps re, hi8 keeps im
        ull kk = hi8 ? k1 : k0;
        ull gg = hi8 ? k0 : k1;
        kk = add2(kk, shfl_xor_ull(gg, 8));
        // stages 3-5: plain butterfly on 1 ull
        kk = add2(kk, shfl_xor_ull(kk, 4));
        kk = add2(kk, shfl_xor_ull(kk, 2));
        kk = add2(kk, shfl_xor_ull(kk, 1));
        // octet leaders write: lane 0:{r0,r1} 8:{i0,i1} 16:{r2,r3} 24:{i2,i3}
        if ((lane & 7) == 0)
            d_P[pb + c * 4 + (lane >> 3)] = kk;
    }
}

// ---------------- combine: merge 5 column-split partials -------------------
__global__ void combine_kernel() {
    __shared__ float sbuf[NSPLIT * 112];
    int rg = blockIdx.x;       // 0..135
    int head = blockIdx.y;
    int t = threadIdx.x;

    const ull* P = d_P + (size_t)(head * NRG + rg) * NSPLIT * 56;
    for (int i = t; i < NSPLIT * 56; i += 128) {
        float a, b;
        upk2(P[i], a, b);
        sbuf[i * 2] = a;
        sbuf[i * 2 + 1] = b;
    }
    __syncthreads();
    if (t >= 104) return;
    int c = t >> 3;
    int comp = (t >> 2) & 1;
    int row = t & 3;

    float M = -1e30f;
#pragma unroll
    for (int k = 0; k < NSPLIT; ++k) M = fmaxf(M, sbuf[k * 112 + 104 + row]);
    float L = 0.f, val = 0.f;
    int fi = (c * 4 + (row >> 1) * 2 + comp) * 2 + (row & 1);
#pragma unroll
    for (int k = 0; k < NSPLIT; ++k) {
        float mk = sbuf[k * 112 + 104 + row];
        float lk = sbuf[k * 112 + 108 + row];
        float s = __expf(mk - M);
        L += lk * s;
        val = fmaf(sbuf[k * 112 + fi], s, val);
    }
    int f = rg * 4 + row;
    if (f < F)
        ((float*)d_O)[(size_t)((head * 13 + c) * F + f) * 2 + comp] = val / L;
}

// ---------------- irfft: Hermitian extend + inverse FFT, real part ---------
__global__ void ifft_kernel(float* __restrict__ out) {
    __shared__ float2 a[1024];
    int sig = blockIdx.x;
    int tid = threadIdx.x;  // 0..511
    const float2* Op = d_O + sig * F;
    float2 o = Op[tid];
    a[__brev(tid) >> 22] = o;
    if (tid > 0) a[__brev(1024 - tid) >> 22] = make_float2(o.x, -o.y);
    if (tid == 0) a[__brev(512) >> 22] = Op[512];
    fft_stages(a, true);
    const float scale = 1.0f / 1024.0f;
    float* op = out + sig * 1024;
    op[tid]       = a[tid].x * scale;
    op[tid + 512] = a[tid + 512].x * scale;
}

// ---------------- launcher --------------------------------------------------
extern "C" void kernel_launch(void* const* d_in, const int* in_sizes, int n_in,
                              void* d_out, int out_size) {
    const float* x  = (const float*)d_in[0];
    const float* wq = (const float*)d_in[1];
    const float* wk = (const float*)d_in[2];
    const float* wv = (const float*)d_in[3];
    float* out = (float*)d_out;

    init_twiddles<<<1, 512>>>();
    fft_forward<<<NSIG, 512>>>(x);
    qkv_kernel<<<dim3(3, H), 256>>>(wq, wk, wv);
    attn_kernel<<<dim3(17 * NSPLIT, H), 256>>>();
    combine_kernel<<<dim3(NRG, H), 128>>>();
    ifft_kernel<<<NSIG, 512>>>(out);
}

// round 11
// speedup vs baseline: 1.4787x; 1.0566x over previous
#include <cuda_runtime.h>
#include <cuda_pipeline_primitives.h>
#include <math.h>

#define H 160           // B*G = 4*40 heads
#define C 13
#define T 1024
#define F 513           // rfft bins
#define NSIG (H * C)    // 2080 signals

typedef unsigned long long ull;

// ---------------- f32x2 packed math helpers (sm_103a FFMA2) ----------------
__device__ __forceinline__ ull pk2(float a, float b) {
    ull r;
    asm("mov.b64 %0, {%1, %2};" : "=l"(r) : "r"(__float_as_uint(a)), "r"(__float_as_uint(b)));
    return r;
}
__device__ __forceinline__ void upk2(ull v, float& a, float& b) {
    unsigned lo, hi;
    asm("mov.b64 {%0, %1}, %2;" : "=r"(lo), "=r"(hi) : "l"(v));
    a = __uint_as_float(lo);
    b = __uint_as_float(hi);
}
__device__ __forceinline__ ull fma2(ull a, ull b, ull c) {
    ull d;
    asm("fma.rn.f32x2 %0, %1, %2, %3;" : "=l"(d) : "l"(a), "l"(b), "l"(c));
    return d;
}
__device__ __forceinline__ ull add2(ull a, ull b) {
    ull d;
    asm("add.rn.f32x2 %0, %1, %2;" : "=l"(d) : "l"(a), "l"(b));
    return d;
}
__device__ __forceinline__ ull shfl_xor_ull(ull v, int m) {
    unsigned lo, hi;
    asm("mov.b64 {%0, %1}, %2;" : "=r"(lo), "=r"(hi) : "l"(v));
    lo = __shfl_xor_sync(0xffffffffu, lo, m);
    hi = __shfl_xor_sync(0xffffffffu, hi, m);
    ull r;
    asm("mov.b64 %0, {%1, %2};" : "=l"(r) : "r"(lo), "r"(hi));
    return r;
}
__device__ __forceinline__ float sqrt_approx(float x) {
    float r;
    asm("sqrt.approx.f32 %0, %1;" : "=f"(r) : "f"(x));
    return r;
}

// ---------------- scratch (device globals: allowed; no runtime alloc) ------
__device__ float2 d_W[512];        // twiddles exp(-2*pi*i*k/1024)
__device__ float2 d_X[H * C * F];  // spectrum, layout [head][c][f]
__device__ float2 d_Q[H * C * F];
__device__ float2 d_K[H * C * F];
__device__ float2 d_V[H * C * F];
__device__ float2 d_O[H * C * F];

// flash partials, ull-packed. Per (head, rowgroup, split) record = 56 ull:
//   c*4 + u, u = 0:{r0,r1} 1:{i0,i1} 2:{r2,r3} 3:{i2,i3}    (c = 0..12)
//   52:{m0,m1} 53:{m2,m3} 54:{l0,l1} 55:{l2,l3}
#define NRG 136        // rowgroups with valid rows (136*4 >= 513)
#define NRGP 144       // padded rowgroups (9 row-blocks * 16 warps)
#define NSPLIT 5
#define KT 104
#define KTP 128
__device__ ull d_P[(size_t)H * NRGP * NSPLIT * 56];   // ~51.6 MB

// ---------------- twiddle init (double trig for precision) -----------------
__global__ void init_twiddles() {
    int k = threadIdx.x;  // 0..511
    double ang = -2.0 * 3.14159265358979323846 * (double)k / 1024.0;
    d_W[k] = make_float2((float)cos(ang), (float)sin(ang));
}

// ---------------- shared radix-2 DIT FFT core (1024 pts, 512 threads) ------
__device__ __forceinline__ void fft_stages(float2* a, bool inverse) {
    int tid = threadIdx.x;
#pragma unroll
    for (int s = 1; s <= 10; ++s) {
        __syncthreads();
        int half = 1 << (s - 1);
        int k = tid & (half - 1);
        int i0 = ((tid >> (s - 1)) << s) + k;
        float2 w = d_W[k << (10 - s)];
        if (inverse) w.y = -w.y;
        float2 u = a[i0];
        float2 v = a[i0 + half];
        float tr = w.x * v.x - w.y * v.y;
        float ti = w.x * v.y + w.y * v.x;
        a[i0]        = make_float2(u.x + tr, u.y + ti);
        a[i0 + half] = make_float2(u.x - tr, u.y - ti);
    }
    __syncthreads();
}

// ---------------- forward rfft: x[sig][0..1023] -> d_X[sig][0..512] --------
__global__ void fft_forward(const float* __restrict__ x) {
    __shared__ float2 a[1024];
    int sig = blockIdx.x;   // head*13 + c
    int tid = threadIdx.x;  // 0..511
    const float* xp = x + sig * 1024;
    a[__brev(tid) >> 22]       = make_float2(xp[tid], 0.f);
    a[__brev(tid + 512) >> 22] = make_float2(xp[tid + 512], 0.f);
    fft_stages(a, false);
    float2* Xp = d_X + sig * F;
    Xp[tid] = a[tid];
    if (tid == 0) Xp[512] = a[512];
}

// ---------------- QKV: [head][c][f] = sum_cin X[head][cin][f] * W[cin][c] --
__global__ void qkv_kernel(const float* __restrict__ wq,
                           const float* __restrict__ wk,
                           const float* __restrict__ wv) {
    __shared__ float ws[3][169];
    int tid = threadIdx.x;
    if (tid < 169) {
        ws[0][tid] = wq[tid];
        ws[1][tid] = wk[tid];
        ws[2][tid] = wv[tid];
    }
    __syncthreads();
    int head = blockIdx.y;
    int f = blockIdx.x * blockDim.x + tid;
    if (f >= F) return;
    float xr[13], xi[13];
#pragma unroll
    for (int c = 0; c < 13; ++c) {
        float2 v = d_X[(head * 13 + c) * F + f];
        xr[c] = v.x;
        xi[c] = v.y;
    }
#pragma unroll 1
    for (int co = 0; co < 13; ++co) {
        float qr = 0.f, qi = 0.f, kr = 0.f, ki = 0.f, vr = 0.f, vi = 0.f;
#pragma unroll
        for (int ci = 0; ci < 13; ++ci) {
            float a = ws[0][ci * 13 + co];
            qr = fmaf(xr[ci], a, qr); qi = fmaf(xi[ci], a, qi);
            float b = ws[1][ci * 13 + co];
            kr = fmaf(xr[ci], b, kr); ki = fmaf(xi[ci], b, ki);
            float g = ws[2][ci * 13 + co];
            vr = fmaf(xr[ci], g, vr); vi = fmaf(xi[ci], g, vi);
        }
        int o = (head * 13 + co) * F + f;
        d_Q[o] = make_float2(qr, qi);
        d_K[o] = make_float2(kr, ki);
        d_V[o] = make_float2(vr, vi);
    }
}

// ---------------- attention (split-column flash, register scores) ----------
// CTA = 64 rows x 104 cols of one head; 16 warps x 4 rows each (512 thr).
// K/V tile filled once per CTA via cp.async (zfill handles padding) and
// serves 64 rows. Lane owns 4 contiguous cols -> LDS.128 pairs.
// Pass-2 lane reduction = value-halving butterfly (12 shfl.b32 per c).
__global__ __launch_bounds__(512, 2) void attn_kernel() {
    __shared__ __align__(16) float2 ksm[13 * KTP];    // 13312 B
    __shared__ __align__(16) float2 vsm[13 * KTP];    // 13312 B
    __shared__ __align__(16) ull    qpk[16 * 13 * 6]; //  9984 B

    int head = blockIdx.y;
    int rb = blockIdx.x / NSPLIT;
    int split = blockIdx.x - rb * NSPLIT;
    int tid = threadIdx.x, lane = tid & 31, w = tid >> 5;  // w = 0..15
    int fbase = rb * 64 + 4 * w;
    int colbase = split * KT;

    // ---- cp.async fill of K,V tile (zero-fill invalid cols) ----
    for (int i = tid; i < 13 * KTP; i += 512) {
        int c = i >> 7, fl = i & 127;
        int f2 = colbase + fl;
        bool ok = (fl < KT) && (f2 < F);
        int go = (head * 13 + c) * F + (ok ? f2 : 0);
        size_t zf = ok ? 0 : 8;
        __pipeline_memcpy_async(&ksm[i], d_K + go, 8, zf);
        __pipeline_memcpy_async(&vsm[i], d_V + go, 8, zf);
    }
    __pipeline_commit();

    // pack Q rows fbase..fbase+3 (lanes 0..12 handle c=lane)
    if (lane < 13) {
        const float2* qp = d_Q + (head * 13 + lane) * F + fbase;
        float2 a0 = (fbase + 0 < F) ? qp[0] : make_float2(0.f, 0.f);
        float2 a1 = (fbase + 1 < F) ? qp[1] : make_float2(0.f, 0.f);
        float2 a2 = (fbase + 2 < F) ? qp[2] : make_float2(0.f, 0.f);
        float2 a3 = (fbase + 3 < F) ? qp[3] : make_float2(0.f, 0.f);
        ull* dst = qpk + (w * 13 + lane) * 6;
        dst[0] = pk2(a0.x, a1.x);   dst[1] = pk2(a2.x, a3.x);
        dst[2] = pk2(a0.y, a1.y);   dst[3] = pk2(a2.y, a3.y);
        dst[4] = pk2(-a0.y, -a1.y); dst[5] = pk2(-a2.y, -a3.y);
    }
    __pipeline_wait_prior(0);
    __syncthreads();

    const ull Z = pk2(0.f, 0.f);
    ull sr01[4], sr23[4], si01[4], si23[4];
#pragma unroll
    for (int j = 0; j < 4; ++j) { sr01[j] = sr23[j] = si01[j] = si23[j] = Z; }

    // ---- pass 1: complex dot products (c outer, 4 contiguous cols/lane) ---
#pragma unroll 1
    for (int c = 0; c < 13; ++c) {
        const ulonglong2* qq = (const ulonglong2*)(qpk + (w * 13 + c) * 6);
        ulonglong2 tx = qq[0];  // {qx01, qx23}
        ulonglong2 ty = qq[1];  // {qy01, qy23}
        ulonglong2 tn = qq[2];  // {-qy01,-qy23}
        const float4* kp = (const float4*)(ksm + c * KTP + 4 * lane);
        float4 kA = kp[0];   // cols 4lane+0, 4lane+1
        float4 kB = kp[1];   // cols 4lane+2, 4lane+3
        float2 k[4] = { make_float2(kA.x, kA.y), make_float2(kA.z, kA.w),
                        make_float2(kB.x, kB.y), make_float2(kB.z, kB.w) };
#pragma unroll
        for (int j = 0; j < 4; ++j) {
            ull kxx = pk2(k[j].x, k[j].x), kyy = pk2(k[j].y, k[j].y);
            sr01[j] = fma2(tx.x, kxx, sr01[j]);  sr01[j] = fma2(tn.x, kyy, sr01[j]);
            sr23[j] = fma2(tx.y, kxx, sr23[j]);  sr23[j] = fma2(tn.y, kyy, sr23[j]);
            si01[j] = fma2(tx.x, kyy, si01[j]);  si01[j] = fma2(ty.x, kxx, si01[j]);
            si23[j] = fma2(tx.y, kyy, si23[j]);  si23[j] = fma2(ty.y, kxx, si23[j]);
        }
    }

    // ---- magnitudes -> scores (repacked into sr01/sr23), per-lane max -----
    float m0 = 0.f, m1 = 0.f, m2 = 0.f, m3 = 0.f;
#pragma unroll
    for (int j = 0; j < 4; ++j) {
        float r0, r1, r2, r3, u0, u1, u2, u3;
        upk2(sr01[j], r0, r1); upk2(sr23[j], r2, r3);
        upk2(si01[j], u0, u1); upk2(si23[j], u2, u3);
        float sc0 = sqrt_approx(fmaf(r0, r0, u0 * u0));
        float sc1 = sqrt_approx(fmaf(r1, r1, u1 * u1));
        float sc2 = sqrt_approx(fmaf(r2, r2, u2 * u2));
        float sc3 = sqrt_approx(fmaf(r3, r3, u3 * u3));
        m0 = fmaxf(m0, sc0); m1 = fmaxf(m1, sc1);
        m2 = fmaxf(m2, sc2); m3 = fmaxf(m3, sc3);
        sr01[j] = pk2(sc0, sc1); sr23[j] = pk2(sc2, sc3);
    }
#pragma unroll
    for (int o = 16; o; o >>= 1) {
        m0 = fmaxf(m0, __shfl_xor_sync(0xffffffffu, m0, o));
        m1 = fmaxf(m1, __shfl_xor_sync(0xffffffffu, m1, o));
        m2 = fmaxf(m2, __shfl_xor_sync(0xffffffffu, m2, o));
        m3 = fmaxf(m3, __shfl_xor_sync(0xffffffffu, m3, o));
    }

    // ---- p = exp(s - m) (masked), l accumulation --------------------------
    float l0 = 0.f, l1 = 0.f, l2 = 0.f, l3 = 0.f;
#pragma unroll
    for (int j = 0; j < 4; ++j) {
        int cl = 4 * lane + j;
        bool valid = (cl < KT) && (colbase + cl < F);
        float s0, s1, s2, s3;
        upk2(sr01[j], s0, s1); upk2(sr23[j], s2, s3);
        float p0 = valid ? __expf(s0 - m0) : 0.f;
        float p1 = valid ? __expf(s1 - m1) : 0.f;
        float p2 = valid ? __expf(s2 - m2) : 0.f;
        float p3 = valid ? __expf(s3 - m3) : 0.f;
        l0 += p0; l1 += p1; l2 += p2; l3 += p3;
        sr01[j] = pk2(p0, p1); sr23[j] = pk2(p2, p3);
    }
#pragma unroll
    for (int o = 16; o; o >>= 1) {
        l0 += __shfl_xor_sync(0xffffffffu, l0, o);
        l1 += __shfl_xor_sync(0xffffffffu, l1, o);
        l2 += __shfl_xor_sync(0xffffffffu, l2, o);
        l3 += __shfl_xor_sync(0xffffffffu, l3, o);
    }

    size_t pb = ((size_t)(head * NRGP + rb * 16 + w) * NSPLIT + split) * 56;
    if (lane == 0) {
        d_P[pb + 52] = pk2(m0, m1);
        d_P[pb + 53] = pk2(m2, m3);
        d_P[pb + 54] = pk2(l0, l1);
        d_P[pb + 55] = pk2(l2, l3);
    }

    // ---- pass 2: partial P @ V per c; value-halving butterfly reduce ------
    bool hi16 = (lane & 16) != 0;
    bool hi8  = (lane & 8) != 0;
#pragma unroll 1
    for (int c = 0; c < 13; ++c) {
        ull ar01 = Z, ar23 = Z, ai01 = Z, ai23 = Z;
        const float4* vp = (const float4*)(vsm + c * KTP + 4 * lane);
        float4 vA = vp[0];
        float4 vB = vp[1];
        float2 v[4] = { make_float2(vA.x, vA.y), make_float2(vA.z, vA.w),
                        make_float2(vB.x, vB.y), make_float2(vB.z, vB.w) };
#pragma unroll
        for (int j = 0; j < 4; ++j) {
            ull vxx = pk2(v[j].x, v[j].x), vyy = pk2(v[j].y, v[j].y);
            ar01 = fma2(sr01[j], vxx, ar01);  ar23 = fma2(sr23[j], vxx, ar23);
            ai01 = fma2(sr01[j], vyy, ai01);  ai23 = fma2(sr23[j], vyy, ai23);
        }
        // stage 1 (xor16): lo keeps rows01, hi keeps rows23
        ull k0 = hi16 ? ar23 : ar01;
        ull k1 = hi16 ? ai23 : ai01;
        ull g0 = hi16 ? ar01 : ar23;
        ull g1 = hi16 ? ai01 : ai23;
        k0 = add2(k0, shfl_xor_ull(g0, 16));
        k1 = add2(k1, shfl_xor_ull(g1, 16));
        // stage 2 (xor8): lo8 keeps re, hi8 keeps im
        ull kk = hi8 ? k1 : k0;
        ull gg = hi8 ? k0 : k1;
        kk = add2(kk, shfl_xor_ull(gg, 8));
        // stages 3-5: plain butterfly on 1 ull
        kk = add2(kk, shfl_xor_ull(kk, 4));
        kk = add2(kk, shfl_xor_ull(kk, 2));
        kk = add2(kk, shfl_xor_ull(kk, 1));
        // octet leaders write: lane 0:{r0,r1} 8:{i0,i1} 16:{r2,r3} 24:{i2,i3}
        if ((lane & 7) == 0)
            d_P[pb + c * 4 + (lane >> 3)] = kk;
    }
}

// ---------------- combine: merge 5 column-split partials -------------------
__global__ void combine_kernel() {
    __shared__ float sbuf[NSPLIT * 112];
    int rg = blockIdx.x;       // 0..135
    int head = blockIdx.y;
    int t = threadIdx.x;

    const ull* P = d_P + (size_t)(head * NRGP + rg) * NSPLIT * 56;
    for (int i = t; i < NSPLIT * 56; i += 128) {
        float a, b;
        upk2(P[i], a, b);
        sbuf[i * 2] = a;
        sbuf[i * 2 + 1] = b;
    }
    __syncthreads();
    if (t >= 104) return;
    int c = t >> 3;
    int comp = (t >> 2) & 1;
    int row = t & 3;

    float M = -1e30f;
#pragma unroll
    for (int k = 0; k < NSPLIT; ++k) M = fmaxf(M, sbuf[k * 112 + 104 + row]);
    float L = 0.f, val = 0.f;
    int fi = (c * 4 + (row >> 1) * 2 + comp) * 2 + (row & 1);
#pragma unroll
    for (int k = 0; k < NSPLIT; ++k) {
        float mk = sbuf[k * 112 + 104 + row];
        float lk = sbuf[k * 112 + 108 + row];
        float s = __expf(mk - M);
        L += lk * s;
        val = fmaf(sbuf[k * 112 + fi], s, val);
    }
    int f = rg * 4 + row;
    if (f < F)
        ((float*)d_O)[(size_t)((head * 13 + c) * F + f) * 2 + comp] = val / L;
}

// ---------------- irfft: Hermitian extend + inverse FFT, real part ---------
__global__ void ifft_kernel(float* __restrict__ out) {
    __shared__ float2 a[1024];
    int sig = blockIdx.x;
    int tid = threadIdx.x;  // 0..511
    const float2* Op = d_O + sig * F;
    float2 o = Op[tid];
    a[__brev(tid) >> 22] = o;
    if (tid > 0) a[__brev(1024 - tid) >> 22] = make_float2(o.x, -o.y);
    if (tid == 0) a[__brev(512) >> 22] = Op[512];
    fft_stages(a, true);
    const float scale = 1.0f / 1024.0f;
    float* op = out + sig * 1024;
    op[tid]       = a[tid].x * scale;
    op[tid + 512] = a[tid + 512].x * scale;
}

// ---------------- launcher --------------------------------------------------
extern "C" void kernel_launch(void* const* d_in, const int* in_sizes, int n_in,
                              void* d_out, int out_size) {
    const float* x  = (const float*)d_in[0];
    const float* wq = (const float*)d_in[1];
    const float* wk = (const float*)d_in[2];
    const float* wv = (const float*)d_in[3];
    float* out = (float*)d_out;

    init_twiddles<<<1, 512>>>();
    fft_forward<<<NSIG, 512>>>(x);
    qkv_kernel<<<dim3(3, H), 256>>>(wq, wk, wv);
    attn_kernel<<<dim3(9 * NSPLIT, H), 512>>>();
    combine_kernel<<<dim3(NRG, H), 128>>>();
    ifft_kernel<<<NSIG, 512>>>(out);
}

// round 14
// speedup vs baseline: 1.5382x; 1.0402x over previous
#include <cuda_runtime.h>
#include <cuda_pipeline_primitives.h>
#include <math.h>

#define H 160           // B*G = 4*40 heads
#define C 13
#define T 1024
#define F 513           // rfft bins
#define FP 514          // padded K/V row pitch (float2) -> 16B-aligned rows
#define NSIG (H * C)    // 2080 signals

typedef unsigned long long ull;

// ---------------- f32x2 packed math helpers (sm_103a FFMA2) ----------------
__device__ __forceinline__ ull pk2(float a, float b) {
    ull r;
    asm("mov.b64 %0, {%1, %2};" : "=l"(r) : "r"(__float_as_uint(a)), "r"(__float_as_uint(b)));
    return r;
}
__device__ __forceinline__ void upk2(ull v, float& a, float& b) {
    unsigned lo, hi;
    asm("mov.b64 {%0, %1}, %2;" : "=r"(lo), "=r"(hi) : "l"(v));
    a = __uint_as_float(lo);
    b = __uint_as_float(hi);
}
__device__ __forceinline__ ull fma2(ull a, ull b, ull c) {
    ull d;
    asm("fma.rn.f32x2 %0, %1, %2, %3;" : "=l"(d) : "l"(a), "l"(b), "l"(c));
    return d;
}
__device__ __forceinline__ ull add2(ull a, ull b) {
    ull d;
    asm("add.rn.f32x2 %0, %1, %2;" : "=l"(d) : "l"(a), "l"(b));
    return d;
}
__device__ __forceinline__ ull shfl_xor_ull(ull v, int m) {
    unsigned lo, hi;
    asm("mov.b64 {%0, %1}, %2;" : "=r"(lo), "=r"(hi) : "l"(v));
    lo = __shfl_xor_sync(0xffffffffu, lo, m);
    hi = __shfl_xor_sync(0xffffffffu, hi, m);
    ull r;
    asm("mov.b64 %0, {%1, %2};" : "=l"(r) : "r"(lo), "r"(hi));
    return r;
}
__device__ __forceinline__ float sqrt_approx(float x) {
    float r;
    asm("sqrt.approx.f32 %0, %1;" : "=f"(r) : "f"(x));
    return r;
}

// ---------------- scratch (device globals: allowed; no runtime alloc) ------
__device__ float2 d_W[512];        // twiddles exp(-2*pi*i*k/1024)
__device__ float2 d_X[H * C * F];  // spectrum, layout [head][c][f]
__device__ float2 d_Q[H * C * F];
__device__ __align__(16) float2 d_K[H * C * FP];  // padded pitch, 16B rows
__device__ __align__(16) float2 d_V[H * C * FP];
__device__ float2 d_O[H * C * F];

// flash partials, ull-packed. Per (head, rowgroup, split) record = 56 ull:
//   c*4 + u, u = 0:{r0,r1} 1:{i0,i1} 2:{r2,r3} 3:{i2,i3}    (c = 0..12)
//   52:{m0,m1} 53:{m2,m3} 54:{l0,l1} 55:{l2,l3}
#define NRG 136        // rowgroups with valid rows (136*4 >= 513)
#define NRGP 144       // padded rowgroups (9 row-blocks * 16 warps)
#define NSPLIT 5
#define KT 104
#define KTP 128
__device__ ull d_P[(size_t)H * NRGP * NSPLIT * 56];   // ~51.6 MB

// ---------------- twiddle init (double trig for precision) -----------------
__global__ void init_twiddles() {
    int k = threadIdx.x;  // 0..511
    double ang = -2.0 * 3.14159265358979323846 * (double)k / 1024.0;
    d_W[k] = make_float2((float)cos(ang), (float)sin(ang));
}

// ---------------- shared radix-2 DIT FFT core (1024 pts, 512 threads) ------
__device__ __forceinline__ void fft_stages(float2* a, bool inverse) {
    int tid = threadIdx.x;
#pragma unroll
    for (int s = 1; s <= 10; ++s) {
        __syncthreads();
        int half = 1 << (s - 1);
        int k = tid & (half - 1);
        int i0 = ((tid >> (s - 1)) << s) + k;
        float2 w = d_W[k << (10 - s)];
        if (inverse) w.y = -w.y;
        float2 u = a[i0];
        float2 v = a[i0 + half];
        float tr = w.x * v.x - w.y * v.y;
        float ti = w.x * v.y + w.y * v.x;
        a[i0]        = make_float2(u.x + tr, u.y + ti);
        a[i0 + half] = make_float2(u.x - tr, u.y - ti);
    }
    __syncthreads();
}

// ---------------- forward rfft: x[sig][0..1023] -> d_X[sig][0..512] --------
__global__ void fft_forward(const float* __restrict__ x) {
    __shared__ float2 a[1024];
    int sig = blockIdx.x;   // head*13 + c
    int tid = threadIdx.x;  // 0..511
    const float* xp = x + sig * 1024;
    a[__brev(tid) >> 22]       = make_float2(xp[tid], 0.f);
    a[__brev(tid + 512) >> 22] = make_float2(xp[tid + 512], 0.f);
    fft_stages(a, false);
    float2* Xp = d_X + sig * F;
    Xp[tid] = a[tid];
    if (tid == 0) Xp[512] = a[512];
}

// ---------------- QKV: [head][c][f] = sum_cin X[head][cin][f] * W[cin][c] --
// Q written with pitch F; K,V with padded pitch FP (16B-aligned rows).
__global__ void qkv_kernel(const float* __restrict__ wq,
                           const float* __restrict__ wk,
                           const float* __restrict__ wv) {
    __shared__ float ws[3][169];
    int tid = threadIdx.x;
    if (tid < 169) {
        ws[0][tid] = wq[tid];
        ws[1][tid] = wk[tid];
        ws[2][tid] = wv[tid];
    }
    __syncthreads();
    int head = blockIdx.y;
    int f = blockIdx.x * blockDim.x + tid;
    if (f >= F) return;
    float xr[13], xi[13];
#pragma unroll
    for (int c = 0; c < 13; ++c) {
        float2 v = d_X[(head * 13 + c) * F + f];
        xr[c] = v.x;
        xi[c] = v.y;
    }
#pragma unroll 1
    for (int co = 0; co < 13; ++co) {
        float qr = 0.f, qi = 0.f, kr = 0.f, ki = 0.f, vr = 0.f, vi = 0.f;
#pragma unroll
        for (int ci = 0; ci < 13; ++ci) {
            float a = ws[0][ci * 13 + co];
            qr = fmaf(xr[ci], a, qr); qi = fmaf(xi[ci], a, qi);
            float b = ws[1][ci * 13 + co];
            kr = fmaf(xr[ci], b, kr); ki = fmaf(xi[ci], b, ki);
            float g = ws[2][ci * 13 + co];
            vr = fmaf(xr[ci], g, vr); vi = fmaf(xi[ci], g, vi);
        }
        d_Q[(head * 13 + co) * F + f]  = make_float2(qr, qi);
        d_K[(head * 13 + co) * FP + f] = make_float2(kr, ki);
        d_V[(head * 13 + co) * FP + f] = make_float2(vr, vi);
    }
}

// ---------------- attention (split-column flash, register scores) ----------
// CTA = 64 rows x 104 cols of one head; 16 warps x 4 rows each (512 thr).
// K/V tile via 16B-granule cp.async (rows 16B-aligned via FP pitch), serves
// 64 rows. Lane owns 4 contiguous cols -> LDS.128 pairs. Butterfly
// (value-halving) warp reductions. tn = ty ^ signmask (ALU).
__global__ __launch_bounds__(512, 2) void attn_kernel() {
    __shared__ __align__(16) float2 ksm[13 * KTP];    // 13312 B
    __shared__ __align__(16) float2 vsm[13 * KTP];    // 13312 B
    __shared__ __align__(16) ull    qpk[16 * 13 * 4]; //  6656 B

    int head = blockIdx.y;
    int rb = blockIdx.x / NSPLIT;
    int split = blockIdx.x - rb * NSPLIT;
    int tid = threadIdx.x, lane = tid & 31, w = tid >> 5;  // w = 0..15
    int fbase = rb * 64 + 4 * w;
    int colbase = split * KT;

    // ---- cp.async fill of K,V tile: 16B granules (2 float2 per op) --------
    // chunk m covers cols {2m, 2m+1}; KT=104 even so in-tile validity is
    // uniform per chunk; only the F boundary (f=512) can split a chunk
    // (padded FP row makes the 16B read legal; zfill masks the pad lane).
    for (int i = tid; i < 13 * (KTP / 2); i += 512) {
        int c = i >> 6, m = i & 63;
        int f2 = colbase + 2 * m;
        size_t zf;
        if ((2 * m < KT) && (f2 < F))
            zf = (f2 + 1 < F) ? 0 : 8;   // full pair, or zero the 2nd half
        else
            zf = 16;                      // fully out of range -> all zeros
        int go = (head * 13 + c) * FP + ((zf == 16) ? 0 : f2);
        __pipeline_memcpy_async(&ksm[c * KTP + 2 * m], d_K + go, 16, zf);
        __pipeline_memcpy_async(&vsm[c * KTP + 2 * m], d_V + go, 16, zf);
    }
    __pipeline_commit();

    // pack Q rows fbase..fbase+3 (lanes 0..12 handle c=lane)
    if (lane < 13) {
        const float2* qp = d_Q + (head * 13 + lane) * F + fbase;
        float2 a0 = (fbase + 0 < F) ? qp[0] : make_float2(0.f, 0.f);
        float2 a1 = (fbase + 1 < F) ? qp[1] : make_float2(0.f, 0.f);
        float2 a2 = (fbase + 2 < F) ? qp[2] : make_float2(0.f, 0.f);
        float2 a3 = (fbase + 3 < F) ? qp[3] : make_float2(0.f, 0.f);
        ull* dst = qpk + (w * 13 + lane) * 4;
        dst[0] = pk2(a0.x, a1.x);   dst[1] = pk2(a2.x, a3.x);
        dst[2] = pk2(a0.y, a1.y);   dst[3] = pk2(a2.y, a3.y);
    }
    __pipeline_wait_prior(0);
    __syncthreads();

    const ull Z = pk2(0.f, 0.f);
    const ull SGN = 0x8000000080000000ULL;
    ull sr01[4], sr23[4], si01[4], si23[4];
#pragma unroll
    for (int j = 0; j < 4; ++j) { sr01[j] = sr23[j] = si01[j] = si23[j] = Z; }

    // ---- pass 1: complex dot products (c outer, 4 contiguous cols/lane) ---
#pragma unroll 1
    for (int c = 0; c < 13; ++c) {
        const ulonglong2* qq = (const ulonglong2*)(qpk + (w * 13 + c) * 4);
        ulonglong2 tx = qq[0];  // {qx01, qx23}
        ulonglong2 ty = qq[1];  // {qy01, qy23}
        ull tnx = ty.x ^ SGN;   // {-qy01}
        ull tny = ty.y ^ SGN;   // {-qy23}
        const float4* kp = (const float4*)(ksm + c * KTP + 4 * lane);
        float4 kA = kp[0];   // cols 4lane+0, 4lane+1
        float4 kB = kp[1];   // cols 4lane+2, 4lane+3
        float2 k[4] = { make_float2(kA.x, kA.y), make_float2(kA.z, kA.w),
                        make_float2(kB.x, kB.y), make_float2(kB.z, kB.w) };
#pragma unroll
        for (int j = 0; j < 4; ++j) {
            ull kxx = pk2(k[j].x, k[j].x), kyy = pk2(k[j].y, k[j].y);
            sr01[j] = fma2(tx.x, kxx, sr01[j]);  sr01[j] = fma2(tnx, kyy, sr01[j]);
            sr23[j] = fma2(tx.y, kxx, sr23[j]);  sr23[j] = fma2(tny, kyy, sr23[j]);
            si01[j] = fma2(tx.x, kyy, si01[j]);  si01[j] = fma2(ty.x, kxx, si01[j]);
            si23[j] = fma2(tx.y, kyy, si23[j]);  si23[j] = fma2(ty.y, kxx, si23[j]);
        }
    }

    // ---- magnitudes -> scores (repacked into sr01/sr23), per-lane max -----
    float m0 = 0.f, m1 = 0.f, m2 = 0.f, m3 = 0.f;
#pragma unroll
    for (int j = 0; j < 4; ++j) {
        float r0, r1, r2, r3, u0, u1, u2, u3;
        upk2(sr01[j], r0, r1); upk2(sr23[j], r2, r3);
        upk2(si01[j], u0, u1); upk2(si23[j], u2, u3);
        float sc0 = sqrt_approx(fmaf(r0, r0, u0 * u0));
        float sc1 = sqrt_approx(fmaf(r1, r1, u1 * u1));
        float sc2 = sqrt_approx(fmaf(r2, r2, u2 * u2));
        float sc3 = sqrt_approx(fmaf(r3, r3, u3 * u3));
        m0 = fmaxf(m0, sc0); m1 = fmaxf(m1, sc1);
        m2 = fmaxf(m2, sc2); m3 = fmaxf(m3, sc3);
        sr01[j] = pk2(sc0, sc1); sr23[j] = pk2(sc2, sc3);
    }
#pragma unroll
    for (int o = 16; o; o >>= 1) {
        m0 = fmaxf(m0, __shfl_xor_sync(0xffffffffu, m0, o));
        m1 = fmaxf(m1, __shfl_xor_sync(0xffffffffu, m1, o));
        m2 = fmaxf(m2, __shfl_xor_sync(0xffffffffu, m2, o));
        m3 = fmaxf(m3, __shfl_xor_sync(0xffffffffu, m3, o));
    }

    // ---- p = exp(s - m) (masked), l accumulation --------------------------
    float l0 = 0.f, l1 = 0.f, l2 = 0.f, l3 = 0.f;
#pragma unroll
    for (int j = 0; j < 4; ++j) {
        int cl = 4 * lane + j;
        bool valid = (cl < KT) && (colbase + cl < F);
        float s0, s1, s2, s3;
        upk2(sr01[j], s0, s1); upk2(sr23[j], s2, s3);
        float p0 = valid ? __expf(s0 - m0) : 0.f;
        float p1 = valid ? __expf(s1 - m1) : 0.f;
        float p2 = valid ? __expf(s2 - m2) : 0.f;
        float p3 = valid ? __expf(s3 - m3) : 0.f;
        l0 += p0; l1 += p1; l2 += p2; l3 += p3;
        sr01[j] = pk2(p0, p1); sr23[j] = pk2(p2, p3);
    }
#pragma unroll
    for (int o = 16; o; o >>= 1) {
        l0 += __shfl_xor_sync(0xffffffffu, l0, o);
        l1 += __shfl_xor_sync(0xffffffffu, l1, o);
        l2 += __shfl_xor_sync(0xffffffffu, l2, o);
        l3 += __shfl_xor_sync(0xffffffffu, l3, o);
    }

    size_t pb = ((size_t)(head * NRGP + rb * 16 + w) * NSPLIT + split) * 56;
    if (lane == 0) {
        d_P[pb + 52] = pk2(m0, m1);
        d_P[pb + 53] = pk2(m2, m3);
        d_P[pb + 54] = pk2(l0, l1);
        d_P[pb + 55] = pk2(l2, l3);
    }

    // ---- pass 2: partial P @ V per c; value-halving butterfly reduce ------
    bool hi16 = (lane & 16) != 0;
    bool hi8  = (lane & 8) != 0;
#pragma unroll 1
    for (int c = 0; c < 13; ++c) {
        ull ar01 = Z, ar23 = Z, ai01 = Z, ai23 = Z;
        const float4* vp = (const float4*)(vsm + c * KTP + 4 * lane);
        float4 vA = vp[0];
        float4 vB = vp[1];
        float2 v[4] = { make_float2(vA.x, vA.y), make_float2(vA.z, vA.w),
                        make_float2(vB.x, vB.y), make_float2(vB.z, vB.w) };
#pragma unroll
        for (int j = 0; j < 4; ++j) {
            ull vxx = pk2(v[j].x, v[j].x), vyy = pk2(v[j].y, v[j].y);
            ar01 = fma2(sr01[j], vxx, ar01);  ar23 = fma2(sr23[j], vxx, ar23);
            ai01 = fma2(sr01[j], vyy, ai01);  ai23 = fma2(sr23[j], vyy, ai23);
        }
        // stage 1 (xor16): lo keeps rows01, hi keeps rows23
        ull k0 = hi16 ? ar23 : ar01;
        ull k1 = hi16 ? ai23 : ai01;
        ull g0 = hi16 ? ar01 : ar23;
        ull g1 = hi16 ? ai01 : ai23;
        k0 = add2(k0, shfl_xor_ull(g0, 16));
        k1 = add2(k1, shfl_xor_ull(g1, 16));
        // stage 2 (xor8): lo8 keeps re, hi8 keeps im
        ull kk = hi8 ? k1 : k0;
        ull gg = hi8 ? k0 : k1;
        kk = add2(kk, shfl_xor_ull(gg, 8));
        // stages 3-5: plain butterfly on 1 ull
        kk = add2(kk, shfl_xor_ull(kk, 4));
        kk = add2(kk, shfl_xor_ull(kk, 2));
        kk = add2(kk, shfl_xor_ull(kk, 1));
        // octet leaders write: lane 0:{r0,r1} 8:{i0,i1} 16:{r2,r3} 24:{i2,i3}
        if ((lane & 7) == 0)
            d_P[pb + c * 4 + (lane >> 3)] = kk;
    }
}

// ---------------- combine: merge 5 column-split partials -------------------
__global__ void combine_kernel() {
    __shared__ float sbuf[NSPLIT * 112];
    int rg = blockIdx.x;       // 0..135
    int head = blockIdx.y;
    int t = threadIdx.x;

    const ull* P = d_P + (size_t)(head * NRGP + rg) * NSPLIT * 56;
    for (int i = t; i < NSPLIT * 56; i += 128) {
        float a, b;
        upk2(P[i], a, b);
        sbuf[i * 2] = a;
        sbuf[i * 2 + 1] = b;
    }
    __syncthreads();
    if (t >= 104) return;
    int c = t >> 3;
    int comp = (t >> 2) & 1;
    int row = t & 3;

    float M = -1e30f;
#pragma unroll
    for (int k = 0; k < NSPLIT; ++k) M = fmaxf(M, sbuf[k * 112 + 104 + row]);
    float L = 0.f, val = 0.f;
    int fi = (c * 4 + (row >> 1) * 2 + comp) * 2 + (row & 1);
#pragma unroll
    for (int k = 0; k < NSPLIT; ++k) {
        float mk = sbuf[k * 112 + 104 + row];
        float lk = sbuf[k * 112 + 108 + row];
        float s = __expf(mk - M);
        L += lk * s;
        val = fmaf(sbuf[k * 112 + fi], s, val);
    }
    int f = rg * 4 + row;
    if (f < F)
        ((float*)d_O)[(size_t)((head * 13 + c) * F + f) * 2 + comp] = val / L;
}

// ---------------- irfft: Hermitian extend + inverse FFT, real part ---------
__global__ void ifft_kernel(float* __restrict__ out) {
    __shared__ float2 a[1024];
    int sig = blockIdx.x;
    int tid = threadIdx.x;  // 0..511
    const float2* Op = d_O + sig * F;
    float2 o = Op[tid];
    a[__brev(tid) >> 22] = o;
    if (tid > 0) a[__brev(1024 - tid) >> 22] = make_float2(o.x, -o.y);
    if (tid == 0) a[__brev(512) >> 22] = Op[512];
    fft_stages(a, true);
    const float scale = 1.0f / 1024.0f;
    float* op = out + sig * 1024;
    op[tid]       = a[tid].x * scale;
    op[tid + 512] = a[tid + 512].x * scale;
}

// ---------------- launcher --------------------------------------------------
extern "C" void kernel_launch(void* const* d_in, const int* in_sizes, int n_in,
                              void* d_out, int out_size) {
    const float* x  = (const float*)d_in[0];
    const float* wq = (const float*)d_in[1];
    const float* wk = (const float*)d_in[2];
    const float* wv = (const float*)d_in[3];
    float* out = (float*)d_out;

    init_twiddles<<<1, 512>>>();
    fft_forward<<<NSIG, 512>>>(x);
    qkv_kernel<<<dim3(3, H), 256>>>(wq, wk, wv);
    attn_kernel<<<dim3(9 * NSPLIT, H), 512>>>();
    combine_kernel<<<dim3(NRG, H), 128>>>();
    ifft_kernel<<<NSIG, 512>>>(out);
}

// round 15
// speedup vs baseline: 1.5471x; 1.0058x over previous
#include <cuda_runtime.h>
#include <cuda_pipeline_primitives.h>
#include <math.h>

#define H 160           // B*G = 4*40 heads
#define C 13
#define T 1024
#define F 513           // rfft bins
#define FP 514          // padded K/V row pitch (float2) -> 16B-aligned rows
#define NSIG (H * C)    // 2080 signals

typedef unsigned long long ull;

// ---------------- f32x2 packed math helpers (sm_103a FFMA2) ----------------
__device__ __forceinline__ ull pk2(float a, float b) {
    ull r;
    asm("mov.b64 %0, {%1, %2};" : "=l"(r) : "r"(__float_as_uint(a)), "r"(__float_as_uint(b)));
    return r;
}
__device__ __forceinline__ void upk2(ull v, float& a, float& b) {
    unsigned lo, hi;
    asm("mov.b64 {%0, %1}, %2;" : "=r"(lo), "=r"(hi) : "l"(v));
    a = __uint_as_float(lo);
    b = __uint_as_float(hi);
}
__device__ __forceinline__ ull fma2(ull a, ull b, ull c) {
    ull d;
    asm("fma.rn.f32x2 %0, %1, %2, %3;" : "=l"(d) : "l"(a), "l"(b), "l"(c));
    return d;
}
__device__ __forceinline__ ull add2(ull a, ull b) {
    ull d;
    asm("add.rn.f32x2 %0, %1, %2;" : "=l"(d) : "l"(a), "l"(b));
    return d;
}
__device__ __forceinline__ ull shfl_xor_ull(ull v, int m) {
    unsigned lo, hi;
    asm("mov.b64 {%0, %1}, %2;" : "=r"(lo), "=r"(hi) : "l"(v));
    lo = __shfl_xor_sync(0xffffffffu, lo, m);
    hi = __shfl_xor_sync(0xffffffffu, hi, m);
    ull r;
    asm("mov.b64 %0, {%1, %2};" : "=l"(r) : "r"(lo), "r"(hi));
    return r;
}
__device__ __forceinline__ float sqrt_approx(float x) {
    float r;
    asm("sqrt.approx.f32 %0, %1;" : "=f"(r) : "f"(x));
    return r;
}

// ---------------- scratch (device globals: allowed; no runtime alloc) ------
__device__ float2 d_W[512];        // twiddles exp(-2*pi*i*k/1024)
__device__ float2 d_X[H * C * F];  // spectrum, layout [head][c][f]
__device__ float2 d_Q[H * C * F];
__device__ __align__(16) float2 d_K[H * C * FP];  // padded pitch, 16B rows
__device__ __align__(16) float2 d_V[H * C * FP];
__device__ float2 d_O[H * C * F];

// flash partials, ull-packed. Per (head, rowgroup, split) record = 56 ull:
//   c*4 + u, u = 0:{r0,r1} 1:{i0,i1} 2:{r2,r3} 3:{i2,i3}    (c = 0..12)
//   52:{m0,m1} 53:{m2,m3} 54:{l0,l1} 55:{l2,l3}
#define NRG 136        // rowgroups with valid rows (136*4 >= 513)
#define NRGP 144       // padded rowgroups (9 row-blocks * 16 warps)
#define NSPLIT 5
#define KT 128         // cols per split: splits {128,128,128,128,1 (+pad)}
#define KTP 128
__device__ ull d_P[(size_t)H * NRGP * NSPLIT * 56];   // ~51.6 MB

// ---------------- twiddle init (double trig for precision) -----------------
__global__ void init_twiddles() {
    int k = threadIdx.x;  // 0..511
    double ang = -2.0 * 3.14159265358979323846 * (double)k / 1024.0;
    d_W[k] = make_float2((float)cos(ang), (float)sin(ang));
}

// ---------------- shared radix-2 DIT FFT core (1024 pts, 512 threads) ------
__device__ __forceinline__ void fft_stages(float2* a, bool inverse) {
    int tid = threadIdx.x;
#pragma unroll
    for (int s = 1; s <= 10; ++s) {
        __syncthreads();
        int half = 1 << (s - 1);
        int k = tid & (half - 1);
        int i0 = ((tid >> (s - 1)) << s) + k;
        float2 w = d_W[k << (10 - s)];
        if (inverse) w.y = -w.y;
        float2 u = a[i0];
        float2 v = a[i0 + half];
        float tr = w.x * v.x - w.y * v.y;
        float ti = w.x * v.y + w.y * v.x;
        a[i0]        = make_float2(u.x + tr, u.y + ti);
        a[i0 + half] = make_float2(u.x - tr, u.y - ti);
    }
    __syncthreads();
}

// ---------------- forward rfft: x[sig][0..1023] -> d_X[sig][0..512] --------
__global__ void fft_forward(const float* __restrict__ x) {
    __shared__ float2 a[1024];
    int sig = blockIdx.x;   // head*13 + c
    int tid = threadIdx.x;  // 0..511
    const float* xp = x + sig * 1024;
    a[__brev(tid) >> 22]       = make_float2(xp[tid], 0.f);
    a[__brev(tid + 512) >> 22] = make_float2(xp[tid + 512], 0.f);
    fft_stages(a, false);
    float2* Xp = d_X + sig * F;
    Xp[tid] = a[tid];
    if (tid == 0) Xp[512] = a[512];
}

// ---------------- QKV: [head][c][f] = sum_cin X[head][cin][f] * W[cin][c] --
// Q written with pitch F; K,V with padded pitch FP (16B-aligned rows).
__global__ void qkv_kernel(const float* __restrict__ wq,
                           const float* __restrict__ wk,
                           const float* __restrict__ wv) {
    __shared__ float ws[3][169];
    int tid = threadIdx.x;
    if (tid < 169) {
        ws[0][tid] = wq[tid];
        ws[1][tid] = wk[tid];
        ws[2][tid] = wv[tid];
    }
    __syncthreads();
    int head = blockIdx.y;
    int f = blockIdx.x * blockDim.x + tid;
    if (f >= F) return;
    float xr[13], xi[13];
#pragma unroll
    for (int c = 0; c < 13; ++c) {
        float2 v = d_X[(head * 13 + c) * F + f];
        xr[c] = v.x;
        xi[c] = v.y;
    }
#pragma unroll 1
    for (int co = 0; co < 13; ++co) {
        float qr = 0.f, qi = 0.f, kr = 0.f, ki = 0.f, vr = 0.f, vi = 0.f;
#pragma unroll
        for (int ci = 0; ci < 13; ++ci) {
            float a = ws[0][ci * 13 + co];
            qr = fmaf(xr[ci], a, qr); qi = fmaf(xi[ci], a, qi);
            float b = ws[1][ci * 13 + co];
            kr = fmaf(xr[ci], b, kr); ki = fmaf(xi[ci], b, ki);
            float g = ws[2][ci * 13 + co];
            vr = fmaf(xr[ci], g, vr); vi = fmaf(xi[ci], g, vi);
        }
        d_Q[(head * 13 + co) * F + f]  = make_float2(qr, qi);
        d_K[(head * 13 + co) * FP + f] = make_float2(kr, ki);
        d_V[(head * 13 + co) * FP + f] = make_float2(vr, vi);
    }
}

// ---------------- attention (split-column flash, register scores) ----------
// CTA = 64 rows x <=128 cols of one head; 16 warps x 4 rows each (512 thr).
// Uneven splits {128,128,128,128,1}: splits 0-3 are mask-free dense tiles.
// Warps whose rows are all >= F exit right after the single __syncthreads.
// K/V tile via 16B-granule cp.async (FP-pitch 16B rows). Lane owns 4
// contiguous cols -> LDS.128 pairs. Value-halving butterfly reductions.
__global__ __launch_bounds__(512, 2) void attn_kernel() {
    __shared__ __align__(16) float2 ksm[13 * KTP];    // 13312 B
    __shared__ __align__(16) float2 vsm[13 * KTP];    // 13312 B
    __shared__ __align__(16) ull    qpk[16 * 13 * 4]; //  6656 B

    int head = blockIdx.y;
    int rb = blockIdx.x / NSPLIT;
    int split = blockIdx.x - rb * NSPLIT;
    int tid = threadIdx.x, lane = tid & 31, w = tid >> 5;  // w = 0..15
    int fbase = rb * 64 + 4 * w;
    int colbase = split * KT;

    // ---- cp.async fill of K,V tile: 16B granules (2 float2 per op) --------
    // chunk m covers cols {2m, 2m+1}; only the F boundary (f=512) splits a
    // chunk (padded FP row makes the 16B read legal; zfill masks pad lane).
    for (int i = tid; i < 13 * (KTP / 2); i += 512) {
        int c = i >> 6, m = i & 63;
        int f2 = colbase + 2 * m;
        size_t zf;
        if (f2 < F)
            zf = (f2 + 1 < F) ? 0 : 8;   // full pair, or zero the 2nd half
        else
            zf = 16;                      // fully out of range -> all zeros
        int go = (head * 13 + c) * FP + ((zf == 16) ? 0 : f2);
        __pipeline_memcpy_async(&ksm[c * KTP + 2 * m], d_K + go, 16, zf);
        __pipeline_memcpy_async(&vsm[c * KTP + 2 * m], d_V + go, 16, zf);
    }
    __pipeline_commit();

    // pack Q rows fbase..fbase+3 (lanes 0..12 handle c=lane)
    if (lane < 13 && fbase < F) {
        const float2* qp = d_Q + (head * 13 + lane) * F + fbase;
        float2 a0 = qp[0];
        float2 a1 = (fbase + 1 < F) ? qp[1] : make_float2(0.f, 0.f);
        float2 a2 = (fbase + 2 < F) ? qp[2] : make_float2(0.f, 0.f);
        float2 a3 = (fbase + 3 < F) ? qp[3] : make_float2(0.f, 0.f);
        ull* dst = qpk + (w * 13 + lane) * 4;
        dst[0] = pk2(a0.x, a1.x);   dst[1] = pk2(a2.x, a3.x);
        dst[2] = pk2(a0.y, a1.y);   dst[3] = pk2(a2.y, a3.y);
    }
    __pipeline_wait_prior(0);
    __syncthreads();

    // rows all out of range -> this warp contributes nothing (only
    // warp-level sync from here on, so returning is safe)
    if (fbase >= F) return;

    const ull Z = pk2(0.f, 0.f);
    const ull SGN = 0x8000000080000000ULL;
    ull sr01[4], sr23[4], si01[4], si23[4];
#pragma unroll
    for (int j = 0; j < 4; ++j) { sr01[j] = sr23[j] = si01[j] = si23[j] = Z; }

    // ---- pass 1: complex dot products (c outer, 4 contiguous cols/lane) ---
#pragma unroll 1
    for (int c = 0; c < 13; ++c) {
        const ulonglong2* qq = (const ulonglong2*)(qpk + (w * 13 + c) * 4);
        ulonglong2 tx = qq[0];  // {qx01, qx23}
        ulonglong2 ty = qq[1];  // {qy01, qy23}
        ull tnx = ty.x ^ SGN;   // {-qy01}
        ull tny = ty.y ^ SGN;   // {-qy23}
        const float4* kp = (const float4*)(ksm + c * KTP + 4 * lane);
        float4 kA = kp[0];   // cols 4lane+0, 4lane+1
        float4 kB = kp[1];   // cols 4lane+2, 4lane+3
        float2 k[4] = { make_float2(kA.x, kA.y), make_float2(kA.z, kA.w),
                        make_float2(kB.x, kB.y), make_float2(kB.z, kB.w) };
#pragma unroll
        for (int j = 0; j < 4; ++j) {
            ull kxx = pk2(k[j].x, k[j].x), kyy = pk2(k[j].y, k[j].y);
            sr01[j] = fma2(tx.x, kxx, sr01[j]);  sr01[j] = fma2(tnx, kyy, sr01[j]);
            sr23[j] = fma2(tx.y, kxx, sr23[j]);  sr23[j] = fma2(tny, kyy, sr23[j]);
            si01[j] = fma2(tx.x, kyy, si01[j]);  si01[j] = fma2(ty.x, kxx, si01[j]);
            si23[j] = fma2(tx.y, kyy, si23[j]);  si23[j] = fma2(ty.y, kxx, si23[j]);
        }
    }

    // ---- magnitudes -> scores (repacked into sr01/sr23), per-lane max -----
    float m0 = 0.f, m1 = 0.f, m2 = 0.f, m3 = 0.f;
#pragma unroll
    for (int j = 0; j < 4; ++j) {
        float r0, r1, r2, r3, u0, u1, u2, u3;
        upk2(sr01[j], r0, r1); upk2(sr23[j], r2, r3);
        upk2(si01[j], u0, u1); upk2(si23[j], u2, u3);
        float sc0 = sqrt_approx(fmaf(r0, r0, u0 * u0));
        float sc1 = sqrt_approx(fmaf(r1, r1, u1 * u1));
        float sc2 = sqrt_approx(fmaf(r2, r2, u2 * u2));
        float sc3 = sqrt_approx(fmaf(r3, r3, u3 * u3));
        m0 = fmaxf(m0, sc0); m1 = fmaxf(m1, sc1);
        m2 = fmaxf(m2, sc2); m3 = fmaxf(m3, sc3);
        sr01[j] = pk2(sc0, sc1); sr23[j] = pk2(sc2, sc3);
    }
#pragma unroll
    for (int o = 16; o; o >>= 1) {
        m0 = fmaxf(m0, __shfl_xor_sync(0xffffffffu, m0, o));
        m1 = fmaxf(m1, __shfl_xor_sync(0xffffffffu, m1, o));
        m2 = fmaxf(m2, __shfl_xor_sync(0xffffffffu, m2, o));
        m3 = fmaxf(m3, __shfl_xor_sync(0xffffffffu, m3, o));
    }

    // ---- p = exp(s - m) (masked only in the last 1-col split) -------------
    float l0 = 0.f, l1 = 0.f, l2 = 0.f, l3 = 0.f;
#pragma unroll
    for (int j = 0; j < 4; ++j) {
        int cl = 4 * lane + j;
        bool valid = (colbase + cl) < F;
        float s0, s1, s2, s3;
        upk2(sr01[j], s0, s1); upk2(sr23[j], s2, s3);
        float p0 = valid ? __expf(s0 - m0) : 0.f;
        float p1 = valid ? __expf(s1 - m1) : 0.f;
        float p2 = valid ? __expf(s2 - m2) : 0.f;
        float p3 = valid ? __expf(s3 - m3) : 0.f;
        l0 += p0; l1 += p1; l2 += p2; l3 += p3;
        sr01[j] = pk2(p0, p1); sr23[j] = pk2(p2, p3);
    }
#pragma unroll
    for (int o = 16; o; o >>= 1) {
        l0 += __shfl_xor_sync(0xffffffffu, l0, o);
        l1 += __shfl_xor_sync(0xffffffffu, l1, o);
        l2 += __shfl_xor_sync(0xffffffffu, l2, o);
        l3 += __shfl_xor_sync(0xffffffffu, l3, o);
    }

    size_t pb = ((size_t)(head * NRGP + rb * 16 + w) * NSPLIT + split) * 56;
    if (lane == 0) {
        d_P[pb + 52] = pk2(m0, m1);
        d_P[pb + 53] = pk2(m2, m3);
        d_P[pb + 54] = pk2(l0, l1);
        d_P[pb + 55] = pk2(l2, l3);
    }

    // ---- pass 2: partial P @ V per c; value-halving butterfly reduce ------
    bool hi16 = (lane & 16) != 0;
    bool hi8  = (lane & 8) != 0;
#pragma unroll 1
    for (int c = 0; c < 13; ++c) {
        ull ar01 = Z, ar23 = Z, ai01 = Z, ai23 = Z;
        const float4* vp = (const float4*)(vsm + c * KTP + 4 * lane);
        float4 vA = vp[0];
        float4 vB = vp[1];
        float2 v[4] = { make_float2(vA.x, vA.y), make_float2(vA.z, vA.w),
                        make_float2(vB.x, vB.y), make_float2(vB.z, vB.w) };
#pragma unroll
        for (int j = 0; j < 4; ++j) {
            ull vxx = pk2(v[j].x, v[j].x), vyy = pk2(v[j].y, v[j].y);
            ar01 = fma2(sr01[j], vxx, ar01);  ar23 = fma2(sr23[j], vxx, ar23);
            ai01 = fma2(sr01[j], vyy, ai01);  ai23 = fma2(sr23[j], vyy, ai23);
        }
        // stage 1 (xor16): lo keeps rows01, hi keeps rows23
        ull k0 = hi16 ? ar23 : ar01;
        ull k1 = hi16 ? ai23 : ai01;
        ull g0 = hi16 ? ar01 : ar23;
        ull g1 = hi16 ? ai01 : ai23;
        k0 = add2(k0, shfl_xor_ull(g0, 16));
        k1 = add2(k1, shfl_xor_ull(g1, 16));
        // stage 2 (xor8): lo8 keeps re, hi8 keeps im
        ull kk = hi8 ? k1 : k0;
        ull gg = hi8 ? k0 : k1;
        kk = add2(kk, shfl_xor_ull(gg, 8));
        // stages 3-5: plain butterfly on 1 ull
        kk = add2(kk, shfl_xor_ull(kk, 4));
        kk = add2(kk, shfl_xor_ull(kk, 2));
        kk = add2(kk, shfl_xor_ull(kk, 1));
        // octet leaders write: lane 0:{r0,r1} 8:{i0,i1} 16:{r2,r3} 24:{i2,i3}
        if ((lane & 7) == 0)
            d_P[pb + c * 4 + (lane >> 3)] = kk;
    }
}

// ---------------- combine: merge 5 column-split partials -------------------
__global__ void combine_kernel() {
    __shared__ float sbuf[NSPLIT * 112];
    int rg = blockIdx.x;       // 0..135
    int head = blockIdx.y;
    int t = threadIdx.x;

    const ull* P = d_P + (size_t)(head * NRGP + rg) * NSPLIT * 56;
    for (int i = t; i < NSPLIT * 56; i += 128) {
        float a, b;
        upk2(P[i], a, b);
        sbuf[i * 2] = a;
        sbuf[i * 2 + 1] = b;
    }
    __syncthreads();
    if (t >= 104) return;
    int c = t >> 3;
    int comp = (t >> 2) & 1;
    int row = t & 3;

    float M = -1e30f;
#pragma unroll
    for (int k = 0; k < NSPLIT; ++k) M = fmaxf(M, sbuf[k * 112 + 104 + row]);
    float L = 0.f, val = 0.f;
    int fi = (c * 4 + (row >> 1) * 2 + comp) * 2 + (row & 1);
#pragma unroll
    for (int k = 0; k < NSPLIT; ++k) {
        float mk = sbuf[k * 112 + 104 + row];
        float lk = sbuf[k * 112 + 108 + row];
        float s = __expf(mk - M);
        L += lk * s;
        val = fmaf(sbuf[k * 112 + fi], s, val);
    }
    int f = rg * 4 + row;
    if (f < F)
        ((float*)d_O)[(size_t)((head * 13 + c) * F + f) * 2 + comp] = val / L;
}

// ---------------- irfft: Hermitian extend + inverse FFT, real part ---------
__global__ void ifft_kernel(float* __restrict__ out) {
    __shared__ float2 a[1024];
    int sig = blockIdx.x;
    int tid = threadIdx.x;  // 0..511
    const float2* Op = d_O + sig * F;
    float2 o = Op[tid];
    a[__brev(tid) >> 22] = o;
    if (tid > 0) a[__brev(1024 - tid) >> 22] = make_float2(o.x, -o.y);
    if (tid == 0) a[__brev(512) >> 22] = Op[512];
    fft_stages(a, true);
    const float scale = 1.0f / 1024.0f;
    float* op = out + sig * 1024;
    op[tid]       = a[tid].x * scale;
    op[tid + 512] = a[tid + 512].x * scale;
}

// ---------------- launcher --------------------------------------------------
extern "C" void kernel_launch(void* const* d_in, const int* in_sizes, int n_in,
                              void* d_out, int out_size) {
    const float* x  = (const float*)d_in[0];
    const float* wq = (const float*)d_in[1];
    const float* wk = (const float*)d_in[2];
    const float* wv = (const float*)d_in[3];
    float* out = (float*)d_out;

    init_twiddles<<<1, 512>>>();
    fft_forward<<<NSIG, 512>>>(x);
    qkv_kernel<<<dim3(3, H), 256>>>(wq, wk, wv);
    attn_kernel<<<dim3(9 * NSPLIT, H), 512>>>();
    combine_kernel<<<dim3(NRG, H), 128>>>();
    ifft_kernel<<<NSIG, 512>>>(out);
}

// round 16
// speedup vs baseline: 1.6311x; 1.0543x over previous
#include <cuda_runtime.h>
#include <cuda_pipeline_primitives.h>
#include <math.h>

#define H 160           // B*G = 4*40 heads
#define C 13
#define T 1024
#define F 513           // rfft bins
#define FP 514          // padded K/V row pitch (float2) -> 16B-aligned rows
#define NSIG (H * C)    // 2080 signals

typedef unsigned long long ull;

// ---------------- f32x2 packed math helpers (sm_103a FFMA2) ----------------
__device__ __forceinline__ ull pk2(float a, float b) {
    ull r;
    asm("mov.b64 %0, {%1, %2};" : "=l"(r) : "r"(__float_as_uint(a)), "r"(__float_as_uint(b)));
    return r;
}
__device__ __forceinline__ void upk2(ull v, float& a, float& b) {
    unsigned lo, hi;
    asm("mov.b64 {%0, %1}, %2;" : "=r"(lo), "=r"(hi) : "l"(v));
    a = __uint_as_float(lo);
    b = __uint_as_float(hi);
}
__device__ __forceinline__ ull fma2(ull a, ull b, ull c) {
    ull d;
    asm("fma.rn.f32x2 %0, %1, %2, %3;" : "=l"(d) : "l"(a), "l"(b), "l"(c));
    return d;
}
__device__ __forceinline__ ull add2(ull a, ull b) {
    ull d;
    asm("add.rn.f32x2 %0, %1, %2;" : "=l"(d) : "l"(a), "l"(b));
    return d;
}
__device__ __forceinline__ ull shfl_xor_ull(ull v, int m) {
    unsigned lo, hi;
    asm("mov.b64 {%0, %1}, %2;" : "=r"(lo), "=r"(hi) : "l"(v));
    lo = __shfl_xor_sync(0xffffffffu, lo, m);
    hi = __shfl_xor_sync(0xffffffffu, hi, m);
    ull r;
    asm("mov.b64 %0, {%1, %2};" : "=l"(r) : "r"(lo), "r"(hi));
    return r;
}
__device__ __forceinline__ float sqrt_approx(float x) {
    float r;
    asm("sqrt.approx.f32 %0, %1;" : "=f"(r) : "f"(x));
    return r;
}

// ---------------- scratch (device globals: allowed; no runtime alloc) ------
__device__ float2 d_W[512];        // twiddles exp(-2*pi*i*k/1024)
__device__ float2 d_X[H * C * F];  // spectrum, layout [head][c][f]
__device__ float2 d_Q[H * C * F];
__device__ __align__(16) float2 d_K[H * C * FP];  // padded pitch, 16B rows
__device__ __align__(16) float2 d_V[H * C * FP];
__device__ float2 d_O[H * C * F];

// flash partials, ull-packed. Per (head, rowgroup, split) record = 56 ull:
//   c*4 + u, u = 0:{r0,r1} 1:{i0,i1} 2:{r2,r3} 3:{i2,i3}    (c = 0..12)
//   52:{m0,m1} 53:{m2,m3} 54:{l0,l1} 55:{l2,l3}
#define NRG 136        // rowgroups with valid rows (136*4 >= 513)
#define NRGP 144       // padded rowgroups (9 row-blocks * 16 warps)
#define NSPLIT 5
#define KT 128         // cols per split: splits {128,128,128,128,1 (+pad)}
#define KTP 128
__device__ ull d_P[(size_t)H * NRGP * NSPLIT * 56];   // ~51.6 MB

// ---------------- twiddle init (double trig for precision) -----------------
__global__ void init_twiddles() {
    int k = threadIdx.x;  // 0..511
    double ang = -2.0 * 3.14159265358979323846 * (double)k / 1024.0;
    d_W[k] = make_float2((float)cos(ang), (float)sin(ang));
}

// ---------------- shared radix-2 DIT FFT core (1024 pts, 512 threads) ------
__device__ __forceinline__ void fft_stages(float2* a, bool inverse) {
    int tid = threadIdx.x;
#pragma unroll
    for (int s = 1; s <= 10; ++s) {
        __syncthreads();
        int half = 1 << (s - 1);
        int k = tid & (half - 1);
        int i0 = ((tid >> (s - 1)) << s) + k;
        float2 w = d_W[k << (10 - s)];
        if (inverse) w.y = -w.y;
        float2 u = a[i0];
        float2 v = a[i0 + half];
        float tr = w.x * v.x - w.y * v.y;
        float ti = w.x * v.y + w.y * v.x;
        a[i0]        = make_float2(u.x + tr, u.y + ti);
        a[i0 + half] = make_float2(u.x - tr, u.y - ti);
    }
    __syncthreads();
}

// ---------------- forward rfft: x[sig][0..1023] -> d_X[sig][0..512] --------
__global__ void fft_forward(const float* __restrict__ x) {
    __shared__ float2 a[1024];
    int sig = blockIdx.x;   // head*13 + c
    int tid = threadIdx.x;  // 0..511
    const float* xp = x + sig * 1024;
    a[__brev(tid) >> 22]       = make_float2(xp[tid], 0.f);
    a[__brev(tid + 512) >> 22] = make_float2(xp[tid + 512], 0.f);
    fft_stages(a, false);
    float2* Xp = d_X + sig * F;
    Xp[tid] = a[tid];
    if (tid == 0) Xp[512] = a[512];
}

// ---------------- QKV: [head][c][f] = sum_cin X[head][cin][f] * W[cin][c] --
// Q written with pitch F; K,V with padded pitch FP (16B-aligned rows).
__global__ void qkv_kernel(const float* __restrict__ wq,
                           const float* __restrict__ wk,
                           const float* __restrict__ wv) {
    __shared__ float ws[3][169];
    int tid = threadIdx.x;
    if (tid < 169) {
        ws[0][tid] = wq[tid];
        ws[1][tid] = wk[tid];
        ws[2][tid] = wv[tid];
    }
    __syncthreads();
    int head = blockIdx.y;
    int f = blockIdx.x * blockDim.x + tid;
    if (f >= F) return;
    float xr[13], xi[13];
#pragma unroll
    for (int c = 0; c < 13; ++c) {
        float2 v = d_X[(head * 13 + c) * F + f];
        xr[c] = v.x;
        xi[c] = v.y;
    }
#pragma unroll 1
    for (int co = 0; co < 13; ++co) {
        float qr = 0.f, qi = 0.f, kr = 0.f, ki = 0.f, vr = 0.f, vi = 0.f;
#pragma unroll
        for (int ci = 0; ci < 13; ++ci) {
            float a = ws[0][ci * 13 + co];
            qr = fmaf(xr[ci], a, qr); qi = fmaf(xi[ci], a, qi);
            float b = ws[1][ci * 13 + co];
            kr = fmaf(xr[ci], b, kr); ki = fmaf(xi[ci], b, ki);
            float g = ws[2][ci * 13 + co];
            vr = fmaf(xr[ci], g, vr); vi = fmaf(xi[ci], g, vi);
        }
        d_Q[(head * 13 + co) * F + f]  = make_float2(qr, qi);
        d_K[(head * 13 + co) * FP + f] = make_float2(kr, ki);
        d_V[(head * 13 + co) * FP + f] = make_float2(vr, vi);
    }
}

// ---------------- attention (split-column flash, register scores) ----------
// CTA = 64 rows x <=128 cols of one head; 16 warps x 4 rows each (512 thr).
// Uneven splits {128,128,128,128,1}: splits 0-3 are mask-free dense tiles.
// Warps whose rows are all >= F exit right after the single __syncthreads.
// K/V tile via 16B-granule cp.async (FP-pitch 16B rows). Lane owns 4
// contiguous cols -> LDS.128 pairs. Value-halving butterfly reductions.
__global__ __launch_bounds__(512, 2) void attn_kernel() {
    __shared__ __align__(16) float2 ksm[13 * KTP];    // 13312 B
    __shared__ __align__(16) float2 vsm[13 * KTP];    // 13312 B
    __shared__ __align__(16) ull    qpk[16 * 13 * 4]; //  6656 B

    int head = blockIdx.y;
    int rb = blockIdx.x / NSPLIT;
    int split = blockIdx.x - rb * NSPLIT;
    int tid = threadIdx.x, lane = tid & 31, w = tid >> 5;  // w = 0..15
    int fbase = rb * 64 + 4 * w;
    int colbase = split * KT;

    // ---- cp.async fill of K,V tile: 16B granules (2 float2 per op) --------
    // chunk m covers cols {2m, 2m+1}; only the F boundary (f=512) splits a
    // chunk (padded FP row makes the 16B read legal; zfill masks pad lane).
    for (int i = tid; i < 13 * (KTP / 2); i += 512) {
        int c = i >> 6, m = i & 63;
        int f2 = colbase + 2 * m;
        size_t zf;
        if (f2 < F)
            zf = (f2 + 1 < F) ? 0 : 8;   // full pair, or zero the 2nd half
        else
            zf = 16;                      // fully out of range -> all zeros
        int go = (head * 13 + c) * FP + ((zf == 16) ? 0 : f2);
        __pipeline_memcpy_async(&ksm[c * KTP + 2 * m], d_K + go, 16, zf);
        __pipeline_memcpy_async(&vsm[c * KTP + 2 * m], d_V + go, 16, zf);
    }
    __pipeline_commit();

    // pack Q rows fbase..fbase+3 (lanes 0..12 handle c=lane)
    if (lane < 13 && fbase < F) {
        const float2* qp = d_Q + (head * 13 + lane) * F + fbase;
        float2 a0 = qp[0];
        float2 a1 = (fbase + 1 < F) ? qp[1] : make_float2(0.f, 0.f);
        float2 a2 = (fbase + 2 < F) ? qp[2] : make_float2(0.f, 0.f);
        float2 a3 = (fbase + 3 < F) ? qp[3] : make_float2(0.f, 0.f);
        ull* dst = qpk + (w * 13 + lane) * 4;
        dst[0] = pk2(a0.x, a1.x);   dst[1] = pk2(a2.x, a3.x);
        dst[2] = pk2(a0.y, a1.y);   dst[3] = pk2(a2.y, a3.y);
    }
    __pipeline_wait_prior(0);
    __syncthreads();

    // rows all out of range -> this warp contributes nothing (only
    // warp-level sync from here on, so returning is safe)
    if (fbase >= F) return;

    const ull Z = pk2(0.f, 0.f);
    const ull SGN = 0x8000000080000000ULL;
    ull sr01[4], sr23[4], si01[4], si23[4];
#pragma unroll
    for (int j = 0; j < 4; ++j) { sr01[j] = sr23[j] = si01[j] = si23[j] = Z; }

    // ---- pass 1: complex dot products (c outer, 4 contiguous cols/lane) ---
#pragma unroll 1
    for (int c = 0; c < 13; ++c) {
        const ulonglong2* qq = (const ulonglong2*)(qpk + (w * 13 + c) * 4);
        ulonglong2 tx = qq[0];  // {qx01, qx23}
        ulonglong2 ty = qq[1];  // {qy01, qy23}
        ull tnx = ty.x ^ SGN;   // {-qy01}
        ull tny = ty.y ^ SGN;   // {-qy23}
        const float4* kp = (const float4*)(ksm + c * KTP + 4 * lane);
        float4 kA = kp[0];   // cols 4lane+0, 4lane+1
        float4 kB = kp[1];   // cols 4lane+2, 4lane+3
        float2 k[4] = { make_float2(kA.x, kA.y), make_float2(kA.z, kA.w),
                        make_float2(kB.x, kB.y), make_float2(kB.z, kB.w) };
#pragma unroll
        for (int j = 0; j < 4; ++j) {
            ull kxx = pk2(k[j].x, k[j].x), kyy = pk2(k[j].y, k[j].y);
            sr01[j] = fma2(tx.x, kxx, sr01[j]);  sr01[j] = fma2(tnx, kyy, sr01[j]);
            sr23[j] = fma2(tx.y, kxx, sr23[j]);  sr23[j] = fma2(tny, kyy, sr23[j]);
            si01[j] = fma2(tx.x, kyy, si01[j]);  si01[j] = fma2(ty.x, kxx, si01[j]);
            si23[j] = fma2(tx.y, kyy, si23[j]);  si23[j] = fma2(ty.y, kxx, si23[j]);
        }
    }

    // ---- magnitudes -> scores (repacked into sr01/sr23), per-lane max -----
    float m0 = 0.f, m1 = 0.f, m2 = 0.f, m3 = 0.f;
#pragma unroll
    for (int j = 0; j < 4; ++j) {
        float r0, r1, r2, r3, u0, u1, u2, u3;
        upk2(sr01[j], r0, r1); upk2(sr23[j], r2, r3);
        upk2(si01[j], u0, u1); upk2(si23[j], u2, u3);
        float sc0 = sqrt_approx(fmaf(r0, r0, u0 * u0));
        float sc1 = sqrt_approx(fmaf(r1, r1, u1 * u1));
        float sc2 = sqrt_approx(fmaf(r2, r2, u2 * u2));
        float sc3 = sqrt_approx(fmaf(r3, r3, u3 * u3));
        m0 = fmaxf(m0, sc0); m1 = fmaxf(m1, sc1);
        m2 = fmaxf(m2, sc2); m3 = fmaxf(m3, sc3);
        sr01[j] = pk2(sc0, sc1); sr23[j] = pk2(sc2, sc3);
    }
#pragma unroll
    for (int o = 16; o; o >>= 1) {
        m0 = fmaxf(m0, __shfl_xor_sync(0xffffffffu, m0, o));
        m1 = fmaxf(m1, __shfl_xor_sync(0xffffffffu, m1, o));
        m2 = fmaxf(m2, __shfl_xor_sync(0xffffffffu, m2, o));
        m3 = fmaxf(m3, __shfl_xor_sync(0xffffffffu, m3, o));
    }

    // ---- p = exp(s - m) (masked only in the last 1-col split) -------------
    float l0 = 0.f, l1 = 0.f, l2 = 0.f, l3 = 0.f;
#pragma unroll
    for (int j = 0; j < 4; ++j) {
        int cl = 4 * lane + j;
        bool valid = (colbase + cl) < F;
        float s0, s1, s2, s3;
        upk2(sr01[j], s0, s1); upk2(sr23[j], s2, s3);
        float p0 = valid ? __expf(s0 - m0) : 0.f;
        float p1 = valid ? __expf(s1 - m1) : 0.f;
        float p2 = valid ? __expf(s2 - m2) : 0.f;
        float p3 = valid ? __expf(s3 - m3) : 0.f;
        l0 += p0; l1 += p1; l2 += p2; l3 += p3;
        sr01[j] = pk2(p0, p1); sr23[j] = pk2(p2, p3);
    }
#pragma unroll
    for (int o = 16; o; o >>= 1) {
        l0 += __shfl_xor_sync(0xffffffffu, l0, o);
        l1 += __shfl_xor_sync(0xffffffffu, l1, o);
        l2 += __shfl_xor_sync(0xffffffffu, l2, o);
        l3 += __shfl_xor_sync(0xffffffffu, l3, o);
    }

    size_t pb = ((size_t)(head * NRGP + rb * 16 + w) * NSPLIT + split) * 56;
    if (lane == 0) {
        d_P[pb + 52] = pk2(m0, m1);
        d_P[pb + 53] = pk2(m2, m3);
        d_P[pb + 54] = pk2(l0, l1);
        d_P[pb + 55] = pk2(l2, l3);
    }

    // ---- pass 2: partial P @ V per c; value-halving butterfly reduce ------
    bool hi16 = (lane & 16) != 0;
    bool hi8  = (lane & 8) != 0;
#pragma unroll 1
    for (int c = 0; c < 13; ++c) {
        ull ar01 = Z, ar23 = Z, ai01 = Z, ai23 = Z;
        const float4* vp = (const float4*)(vsm + c * KTP + 4 * lane);
        float4 vA = vp[0];
        float4 vB = vp[1];
        float2 v[4] = { make_float2(vA.x, vA.y), make_float2(vA.z, vA.w),
                        make_float2(vB.x, vB.y), make_float2(vB.z, vB.w) };
#pragma unroll
        for (int j = 0; j < 4; ++j) {
            ull vxx = pk2(v[j].x, v[j].x), vyy = pk2(v[j].y, v[j].y);
            ar01 = fma2(sr01[j], vxx, ar01);  ar23 = fma2(sr23[j], vxx, ar23);
            ai01 = fma2(sr01[j], vyy, ai01);  ai23 = fma2(sr23[j], vyy, ai23);
        }
        // stage 1 (xor16): lo keeps rows01, hi keeps rows23
        ull k0 = hi16 ? ar23 : ar01;
        ull k1 = hi16 ? ai23 : ai01;
        ull g0 = hi16 ? ar01 : ar23;
        ull g1 = hi16 ? ai01 : ai23;
        k0 = add2(k0, shfl_xor_ull(g0, 16));
        k1 = add2(k1, shfl_xor_ull(g1, 16));
        // stage 2 (xor8): lo8 keeps re, hi8 keeps im
        ull kk = hi8 ? k1 : k0;
        ull gg = hi8 ? k0 : k1;
        kk = add2(kk, shfl_xor_ull(gg, 8));
        // stages 3-5: plain butterfly on 1 ull
        kk = add2(kk, shfl_xor_ull(kk, 4));
        kk = add2(kk, shfl_xor_ull(kk, 2));
        kk = add2(kk, shfl_xor_ull(kk, 1));
        // octet leaders write: lane 0:{r0,r1} 8:{i0,i1} 16:{r2,r3} 24:{i2,i3}
        if ((lane & 7) == 0)
            d_P[pb + c * 4 + (lane >> 3)] = kk;
    }
}

// ---------------- combine: merge 5 column-split partials -------------------
__global__ void combine_kernel() {
    __shared__ float sbuf[NSPLIT * 112];
    int rg = blockIdx.x;       // 0..135
    int head = blockIdx.y;
    int t = threadIdx.x;

    const ull* P = d_P + (size_t)(head * NRGP + rg) * NSPLIT * 56;
    for (int i = t; i < NSPLIT * 56; i += 128) {
        float a, b;
        upk2(P[i], a, b);
        sbuf[i * 2] = a;
        sbuf[i * 2 + 1] = b;
    }
    __syncthreads();
    if (t >= 104) return;
    int c = t >> 3;
    int comp = (t >> 2) & 1;
    int row = t & 3;

    float M = -1e30f;
#pragma unroll
    for (int k = 0; k < NSPLIT; ++k) M = fmaxf(M, sbuf[k * 112 + 104 + row]);
    float L = 0.f, val = 0.f;
    int fi = (c * 4 + (row >> 1) * 2 + comp) * 2 + (row & 1);
#pragma unroll
    for (int k = 0; k < NSPLIT; ++k) {
        float mk = sbuf[k * 112 + 104 + row];
        float lk = sbuf[k * 112 + 108 + row];
        float s = __expf(mk - M);
        L += lk * s;
        val = fmaf(sbuf[k * 112 + fi], s, val);
    }
    int f = rg * 4 + row;
    if (f < F)
        ((float*)d_O)[(size_t)((head * 13 + c) * F + f) * 2 + comp] = val / L;
}

// ---------------- irfft: Hermitian extend + inverse FFT, real part ---------
__global__ void ifft_kernel(float* __restrict__ out) {
    __shared__ float2 a[1024];
    int sig = blockIdx.x;
    int tid = threadIdx.x;  // 0..511
    const float2* Op = d_O + sig * F;
    float2 o = Op[tid];
    a[__brev(tid) >> 22] = o;
    if (tid > 0) a[__brev(1024 - tid) >> 22] = make_float2(o.x, -o.y);
    if (tid == 0) a[__brev(512) >> 22] = Op[512];
    fft_stages(a, true);
    const float scale = 1.0f / 1024.0f;
    float* op = out + sig * 1024;
    op[tid]       = a[tid].x * scale;
    op[tid + 512] = a[tid + 512].x * scale;
}

// ---------------- launcher --------------------------------------------------
extern "C" void kernel_launch(void* const* d_in, const int* in_sizes, int n_in,
                              void* d_out, int out_size) {
    const float* x  = (const float*)d_in[0];
    const float* wq = (const float*)d_in[1];
    const float* wk = (const float*)d_in[2];
    const float* wv = (const float*)d_in[3];
    float* out = (float*)d_out;

    init_twiddles<<<1, 512>>>();
    fft_forward<<<NSIG, 512>>>(x);
    qkv_kernel<<<dim3(3, H), 256>>>(wq, wk, wv);
    attn_kernel<<<dim3(9 * NSPLIT, H), 512>>>();
    combine_kernel<<<dim3(NRG, H), 128>>>();
    ifft_kernel<<<NSIG, 512>>>(out);
}